// round 1
// baseline (speedup 1.0000x reference)
#include <cuda_runtime.h>
#include <math.h>

#define B_ 4
#define N_ 256
#define D_ 128
#define MTOT (B_*N_*N_)            // 262144 rows
#define ELEMS ((size_t)MTOT*D_)    // 33554432

// -------- scratch (device globals; no allocations allowed) --------
__device__ float g_zl[ELEMS];    // layernormed z            (b,i,j,d)
__device__ float g_at[ELEMS];    // gated proj a, transposed (b,d,i,k)
__device__ float g_bt[ELEMS];    // gated proj b, transposed (b,d,j,k)
__device__ float g_ot[ELEMS];    // triangle result          (b,d,i,j)
__device__ float g_on[ELEMS];    // triangle result natural  (b,i,j,d)
__device__ float g_gate[ELEMS];  // sigmoid(zl@wog^T+bog)    (b,i,j,d)

__device__ __forceinline__ float sigmoidf_(float x) { return 1.0f / (1.0f + __expf(-x)); }

// ============================================================
// K1: LayerNorm over last dim (D=128). 1 warp per row, 8 rows/block.
// ============================================================
__global__ void ln_kernel(const float* __restrict__ z,
                          const float* __restrict__ gin,
                          const float* __restrict__ bin)
{
    int w = threadIdx.x >> 5, lane = threadIdx.x & 31;
    size_t row = (size_t)blockIdx.x * 8 + w;
    const float* x = z + row * D_;
    float v0 = x[lane], v1 = x[lane + 32], v2 = x[lane + 64], v3 = x[lane + 96];
    float s = v0 + v1 + v2 + v3;
    #pragma unroll
    for (int o = 16; o > 0; o >>= 1) s += __shfl_xor_sync(0xffffffffu, s, o);
    float mean = s * (1.0f / D_);
    float d0 = v0 - mean, d1 = v1 - mean, d2 = v2 - mean, d3 = v3 - mean;
    float q = d0*d0 + d1*d1 + d2*d2 + d3*d3;
    #pragma unroll
    for (int o = 16; o > 0; o >>= 1) q += __shfl_xor_sync(0xffffffffu, q, o);
    float inv = rsqrtf(q * (1.0f / D_) + 1e-5f);
    float* y = g_zl + row * D_;
    y[lane]      = d0 * inv * gin[lane]      + bin[lane];
    y[lane + 32] = d1 * inv * gin[lane + 32] + bin[lane + 32];
    y[lane + 64] = d2 * inv * gin[lane + 64] + bin[lane + 64];
    y[lane + 96] = d3 * inv * gin[lane + 96] + bin[lane + 96];
}

// ============================================================
// K2/K3: gated projection pair, output written TRANSPOSED to (b,d,i,k).
// Block: 64 rows (fixed b,i; 64 consecutive k) x all 128 out-d in 4 chunks of 32.
// 256 threads, microtile 4m x 2o per GEMM.
// dyn smem: As[64][129] + Ws[2][32][129]  (Os staging overlays Ws)
// ============================================================
__global__ void proj_pair_kernel(int sel,
                                 const float* __restrict__ Wg, const float* __restrict__ bgv,
                                 const float* __restrict__ Wp, const float* __restrict__ bpv)
{
    extern __shared__ float sm[];
    float* As  = sm;                 // 64*129
    float* Wsm = sm + 64 * 129;      // 2*32*129
    float* outT = sel ? g_bt : g_at;

    const int tid = threadIdx.x;
    const size_t m0 = (size_t)blockIdx.x * 64;
    const int b   = (int)(m0 >> 16);
    const int ii  = (int)((m0 >> 8) & 255);
    const int kk0 = (int)(m0 & 255);

    const float* zrow = g_zl + m0 * D_;
    #pragma unroll
    for (int i = 0; i < 8; i++) {
        int lin = tid + i * 256;               // 2048 float4 total
        int m = lin >> 5, kq = (lin & 31) << 2;
        float4 v = *reinterpret_cast<const float4*>(zrow + m * 128 + kq);
        float* d = As + m * 129 + kq;
        d[0] = v.x; d[1] = v.y; d[2] = v.z; d[3] = v.w;
    }
    __syncthreads();

    const int mg = tid >> 4, og = tid & 15;
    const int mb = mg * 4, ol = og * 2;

    for (int c = 0; c < 4; c++) {
        #pragma unroll
        for (int i = 0; i < 4; i++) {
            int lin = tid + i * 256;           // 1024 float4 per matrix
            int o = lin >> 5, kq = (lin & 31) << 2;
            float4 vg = *reinterpret_cast<const float4*>(Wg + (c * 32 + o) * 128 + kq);
            float4 vp = *reinterpret_cast<const float4*>(Wp + (c * 32 + o) * 128 + kq);
            float* dg = Wsm + o * 129 + kq;
            float* dp = Wsm + 32 * 129 + o * 129 + kq;
            dg[0] = vg.x; dg[1] = vg.y; dg[2] = vg.z; dg[3] = vg.w;
            dp[0] = vp.x; dp[1] = vp.y; dp[2] = vp.z; dp[3] = vp.w;
        }
        __syncthreads();

        float aG[4][2] = {}, aP[4][2] = {};
        #pragma unroll 8
        for (int k = 0; k < 128; k++) {
            float a0 = As[(mb + 0) * 129 + k];
            float a1 = As[(mb + 1) * 129 + k];
            float a2 = As[(mb + 2) * 129 + k];
            float a3 = As[(mb + 3) * 129 + k];
            float w0 = Wsm[ol * 129 + k];
            float w1 = Wsm[(ol + 1) * 129 + k];
            float p0 = Wsm[32 * 129 + ol * 129 + k];
            float p1 = Wsm[32 * 129 + (ol + 1) * 129 + k];
            aG[0][0] += a0 * w0; aG[0][1] += a0 * w1;
            aG[1][0] += a1 * w0; aG[1][1] += a1 * w1;
            aG[2][0] += a2 * w0; aG[2][1] += a2 * w1;
            aG[3][0] += a3 * w0; aG[3][1] += a3 * w1;
            aP[0][0] += a0 * p0; aP[0][1] += a0 * p1;
            aP[1][0] += a1 * p0; aP[1][1] += a1 * p1;
            aP[2][0] += a2 * p0; aP[2][1] += a2 * p1;
            aP[3][0] += a3 * p0; aP[3][1] += a3 * p1;
        }
        __syncthreads();  // done reading Wsm; safe to overlay with Os

        float* Os = Wsm;  // [32][65]
        #pragma unroll
        for (int i = 0; i < 4; i++)
            #pragma unroll
            for (int j = 0; j < 2; j++) {
                int o = c * 32 + ol + j;
                float val = sigmoidf_(aG[i][j] + bgv[o]) * (aP[i][j] + bpv[o]);
                Os[(ol + j) * 65 + mb + i] = val;
            }
        __syncthreads();

        #pragma unroll
        for (int i = 0; i < 8; i++) {
            int lin = tid + i * 256;           // 2048 elems
            int o = lin >> 6, m = lin & 63;
            outT[((size_t)(b * 128 + c * 32 + o) * 256 + ii) * 256 + kk0 + m] = Os[o * 65 + m];
        }
        __syncthreads();
    }
}

// ============================================================
// K4: gate projection sigmoid(zl@wog^T+bog) -> g_gate (natural layout)
// dyn smem: As[64][129] + Ws[32][129]
// ============================================================
__global__ void proj_gate_kernel(const float* __restrict__ Wg, const float* __restrict__ bgv)
{
    extern __shared__ float sm[];
    float* As  = sm;
    float* Wsm = sm + 64 * 129;

    const int tid = threadIdx.x;
    const size_t m0 = (size_t)blockIdx.x * 64;
    const float* zrow = g_zl + m0 * D_;
    #pragma unroll
    for (int i = 0; i < 8; i++) {
        int lin = tid + i * 256;
        int m = lin >> 5, kq = (lin & 31) << 2;
        float4 v = *reinterpret_cast<const float4*>(zrow + m * 128 + kq);
        float* d = As + m * 129 + kq;
        d[0] = v.x; d[1] = v.y; d[2] = v.z; d[3] = v.w;
    }
    __syncthreads();

    const int mg = tid >> 4, og = tid & 15;
    const int mb = mg * 4, ol = og * 2;

    for (int c = 0; c < 4; c++) {
        #pragma unroll
        for (int i = 0; i < 4; i++) {
            int lin = tid + i * 256;
            int o = lin >> 5, kq = (lin & 31) << 2;
            float4 vg = *reinterpret_cast<const float4*>(Wg + (c * 32 + o) * 128 + kq);
            float* dg = Wsm + o * 129 + kq;
            dg[0] = vg.x; dg[1] = vg.y; dg[2] = vg.z; dg[3] = vg.w;
        }
        __syncthreads();

        float aG[4][2] = {};
        #pragma unroll 8
        for (int k = 0; k < 128; k++) {
            float a0 = As[(mb + 0) * 129 + k];
            float a1 = As[(mb + 1) * 129 + k];
            float a2 = As[(mb + 2) * 129 + k];
            float a3 = As[(mb + 3) * 129 + k];
            float w0 = Wsm[ol * 129 + k];
            float w1 = Wsm[(ol + 1) * 129 + k];
            aG[0][0] += a0 * w0; aG[0][1] += a0 * w1;
            aG[1][0] += a1 * w0; aG[1][1] += a1 * w1;
            aG[2][0] += a2 * w0; aG[2][1] += a2 * w1;
            aG[3][0] += a3 * w0; aG[3][1] += a3 * w1;
        }
        __syncthreads();

        int o = c * 32 + ol;
        float b0 = bgv[o], b1 = bgv[o + 1];
        #pragma unroll
        for (int i = 0; i < 4; i++) {
            size_t row = m0 + mb + i;
            float2 r;
            r.x = sigmoidf_(aG[i][0] + b0);
            r.y = sigmoidf_(aG[i][1] + b1);
            *reinterpret_cast<float2*>(g_gate + row * 128 + o) = r;
        }
    }
}

// ============================================================
// K5: triangle einsum as 512 batched SGEMM-NT 256x256x256 on (b,d) slices.
// 64x64 tile, K-tile 32, 4x4 microtile, 256 threads.
// ============================================================
__global__ void tri_kernel()
{
    __shared__ float As[64][33];
    __shared__ float Bs[64][33];
    const int batch = blockIdx.z;                    // b*128 + d
    const float* Ab = g_at + (size_t)batch * 65536;
    const float* Bb = g_bt + (size_t)batch * 65536;
    float*       Cb = g_ot + (size_t)batch * 65536;
    const int i0 = blockIdx.y * 64, j0 = blockIdx.x * 64;
    const int tid = threadIdx.x;
    const int ig = tid >> 4, jg = tid & 15;

    float acc[4][4] = {};
    for (int kt = 0; kt < 256; kt += 32) {
        #pragma unroll
        for (int i = 0; i < 2; i++) {
            int lin = tid + i * 256;                 // 512 float4 per matrix
            int rr = lin >> 3, kq = (lin & 7) << 2;
            float4 va = *reinterpret_cast<const float4*>(Ab + (i0 + rr) * 256 + kt + kq);
            float4 vb = *reinterpret_cast<const float4*>(Bb + (j0 + rr) * 256 + kt + kq);
            As[rr][kq] = va.x; As[rr][kq + 1] = va.y; As[rr][kq + 2] = va.z; As[rr][kq + 3] = va.w;
            Bs[rr][kq] = vb.x; Bs[rr][kq + 1] = vb.y; Bs[rr][kq + 2] = vb.z; Bs[rr][kq + 3] = vb.w;
        }
        __syncthreads();
        #pragma unroll
        for (int k = 0; k < 32; k++) {
            float av[4], bv[4];
            #pragma unroll
            for (int ii = 0; ii < 4; ii++) av[ii] = As[ig * 4 + ii][k];
            #pragma unroll
            for (int jj = 0; jj < 4; jj++) bv[jj] = Bs[jg * 4 + jj][k];
            #pragma unroll
            for (int ii = 0; ii < 4; ii++)
                #pragma unroll
                for (int jj = 0; jj < 4; jj++) acc[ii][jj] += av[ii] * bv[jj];
        }
        __syncthreads();
    }
    #pragma unroll
    for (int ii = 0; ii < 4; ii++) {
        float4 v = make_float4(acc[ii][0], acc[ii][1], acc[ii][2], acc[ii][3]);
        *reinterpret_cast<float4*>(Cb + (i0 + ig * 4 + ii) * 256 + j0 + jg * 4) = v;
    }
}

// ============================================================
// K6: transpose (b,d,p) -> (b,p,d) with 32x32 tiles.
// ============================================================
__global__ void transpose_kernel()
{
    __shared__ float t[32][33];
    const int b = blockIdx.z;
    const int p0 = blockIdx.x * 32, d0 = blockIdx.y * 32;
    const int tx = threadIdx.x & 31, ty = threadIdx.x >> 5;   // 256 threads: ty 0..7
    const float* src = g_ot + (size_t)b * 128 * 65536;
    float*       dst = g_on + (size_t)b * 65536 * 128;
    #pragma unroll
    for (int i = 0; i < 4; i++) {
        int d = d0 + ty + i * 8;
        t[ty + i * 8][tx] = src[(size_t)d * 65536 + p0 + tx];
    }
    __syncthreads();
    #pragma unroll
    for (int i = 0; i < 4; i++) {
        int p = p0 + ty + i * 8;
        dst[(size_t)p * 128 + d0 + tx] = t[tx][ty + i * 8];
    }
}

// ============================================================
// K7: LayerNorm(out)*g_out+b_out, then @wop^T+bop, then * gate -> d_out
// dyn smem: As[64][129] + Ws[32][129] + red[640]
// ============================================================
__global__ void final_kernel(const float* __restrict__ gout, const float* __restrict__ bout,
                             const float* __restrict__ Wop, const float* __restrict__ bop,
                             float* __restrict__ outp)
{
    extern __shared__ float sm[];
    float* As  = sm;                  // 64*129
    float* Wsm = sm + 64 * 129;       // 32*129
    float* red = Wsm + 32 * 129;      // 640

    const int tid = threadIdx.x;
    const size_t m0 = (size_t)blockIdx.x * 64;
    const float* xrow = g_on + m0 * D_;
    #pragma unroll
    for (int i = 0; i < 8; i++) {
        int lin = tid + i * 256;
        int m = lin >> 5, kq = (lin & 31) << 2;
        float4 v = *reinterpret_cast<const float4*>(xrow + m * 128 + kq);
        float* d = As + m * 129 + kq;
        d[0] = v.x; d[1] = v.y; d[2] = v.z; d[3] = v.w;
    }
    __syncthreads();

    // layernorm stats: 4 threads per row
    const int r = tid >> 2, part = tid & 3;
    {
        float s1 = 0.f, s2 = 0.f;
        #pragma unroll
        for (int k = part * 32; k < part * 32 + 32; k++) {
            float v = As[r * 129 + k];
            s1 += v; s2 += v * v;
        }
        red[r * 4 + part] = s1;
        red[256 + r * 4 + part] = s2;
    }
    __syncthreads();
    if (tid < 64) {
        float a  = red[tid * 4] + red[tid * 4 + 1] + red[tid * 4 + 2] + red[tid * 4 + 3];
        float b2 = red[256 + tid * 4] + red[256 + tid * 4 + 1] + red[256 + tid * 4 + 2] + red[256 + tid * 4 + 3];
        float mean = a * (1.0f / 128.0f);
        float var  = b2 * (1.0f / 128.0f) - mean * mean;
        red[512 + tid] = mean;
        red[576 + tid] = rsqrtf(var + 1e-5f);
    }
    __syncthreads();
    {
        float mean = red[512 + r], inv = red[576 + r];
        #pragma unroll
        for (int k = part * 32; k < part * 32 + 32; k++) {
            float v = As[r * 129 + k];
            As[r * 129 + k] = (v - mean) * inv * gout[k] + bout[k];
        }
    }
    __syncthreads();

    const int mg = tid >> 4, og = tid & 15;
    const int mb = mg * 4, ol = og * 2;

    for (int c = 0; c < 4; c++) {
        #pragma unroll
        for (int i = 0; i < 4; i++) {
            int lin = tid + i * 256;
            int o = lin >> 5, kq = (lin & 31) << 2;
            float4 vg = *reinterpret_cast<const float4*>(Wop + (c * 32 + o) * 128 + kq);
            float* dg = Wsm + o * 129 + kq;
            dg[0] = vg.x; dg[1] = vg.y; dg[2] = vg.z; dg[3] = vg.w;
        }
        __syncthreads();

        float acc[4][2] = {};
        #pragma unroll 8
        for (int k = 0; k < 128; k++) {
            float a0 = As[(mb + 0) * 129 + k];
            float a1 = As[(mb + 1) * 129 + k];
            float a2 = As[(mb + 2) * 129 + k];
            float a3 = As[(mb + 3) * 129 + k];
            float w0 = Wsm[ol * 129 + k];
            float w1 = Wsm[(ol + 1) * 129 + k];
            acc[0][0] += a0 * w0; acc[0][1] += a0 * w1;
            acc[1][0] += a1 * w0; acc[1][1] += a1 * w1;
            acc[2][0] += a2 * w0; acc[2][1] += a2 * w1;
            acc[3][0] += a3 * w0; acc[3][1] += a3 * w1;
        }
        __syncthreads();

        int o = c * 32 + ol;
        float b0 = bop[o], b1 = bop[o + 1];
        #pragma unroll
        for (int i = 0; i < 4; i++) {
            size_t row = m0 + mb + i;
            float2 gt = *reinterpret_cast<const float2*>(g_gate + row * 128 + o);
            float2 res;
            res.x = gt.x * (acc[i][0] + b0);
            res.y = gt.y * (acc[i][1] + b1);
            *reinterpret_cast<float2*>(outp + row * 128 + o) = res;
        }
    }
}

// ============================================================
// launch
// ============================================================
extern "C" void kernel_launch(void* const* d_in, const int* in_sizes, int n_in,
                              void* d_out, int out_size)
{
    const float* z    = (const float*)d_in[0];
    const float* gin  = (const float*)d_in[1];
    const float* bin  = (const float*)d_in[2];
    const float* wpa  = (const float*)d_in[3];
    const float* bpa  = (const float*)d_in[4];
    const float* wga  = (const float*)d_in[5];
    const float* bga  = (const float*)d_in[6];
    const float* wpb  = (const float*)d_in[7];
    const float* bpb  = (const float*)d_in[8];
    const float* wgb  = (const float*)d_in[9];
    const float* bgb  = (const float*)d_in[10];
    const float* gout = (const float*)d_in[11];
    const float* bout = (const float*)d_in[12];
    const float* wop  = (const float*)d_in[13];
    const float* bop  = (const float*)d_in[14];
    const float* wog  = (const float*)d_in[15];
    const float* bog  = (const float*)d_in[16];
    float* outp = (float*)d_out;

    const int SMEM_PP = (64 * 129 + 2 * 32 * 129) * 4;       // 66048
    const int SMEM_PG = (64 * 129 + 32 * 129) * 4;           // 49536
    const int SMEM_FN = (64 * 129 + 32 * 129 + 640) * 4;     // 52096
    cudaFuncSetAttribute(proj_pair_kernel, cudaFuncAttributeMaxDynamicSharedMemorySize, SMEM_PP);
    cudaFuncSetAttribute(proj_gate_kernel, cudaFuncAttributeMaxDynamicSharedMemorySize, SMEM_PG);
    cudaFuncSetAttribute(final_kernel,     cudaFuncAttributeMaxDynamicSharedMemorySize, SMEM_FN);

    ln_kernel<<<MTOT / 8, 256>>>(z, gin, bin);
    proj_pair_kernel<<<MTOT / 64, 256, SMEM_PP>>>(0, wga, bga, wpa, bpa);  // -> g_at
    proj_pair_kernel<<<MTOT / 64, 256, SMEM_PP>>>(1, wgb, bgb, wpb, bpb);  // -> g_bt
    proj_gate_kernel<<<MTOT / 64, 256, SMEM_PG>>>(wog, bog);               // -> g_gate
    tri_kernel<<<dim3(4, 4, B_ * D_), 256>>>();                            // -> g_ot
    transpose_kernel<<<dim3(N_ * N_ / 32, D_ / 32, B_), 256>>>();          // -> g_on
    final_kernel<<<MTOT / 64, 256, SMEM_FN>>>(gout, bout, wop, bop, outp); // -> d_out
}

// round 3
// speedup vs baseline: 1.3417x; 1.3417x over previous
#include <cuda_runtime.h>
#include <cuda_bf16.h>
#include <stdint.h>

#define ELEMS ((size_t)4*256*256*128)   // 33.5M

// ---------------- scratch ----------------
__device__ __align__(16) __nv_bfloat16 g_at_hi[ELEMS];
__device__ __align__(16) __nv_bfloat16 g_at_lo[ELEMS];
__device__ __align__(16) __nv_bfloat16 g_bt_hi[ELEMS];
__device__ __align__(16) __nv_bfloat16 g_bt_lo[ELEMS];
__device__ __align__(16) float g_gate[ELEMS];
__device__ __align__(16) float g_ot[ELEMS];

// ---------------- helpers ----------------
__device__ __forceinline__ uint32_t smem_u32(const void* p){
    uint32_t a;
    asm("{ .reg .u64 t; cvta.to.shared.u64 t, %1; cvt.u32.u64 %0, t; }" : "=r"(a) : "l"(p));
    return a;
}
__device__ __forceinline__ void ldsm_x4(uint32_t* r, uint32_t a){
    asm volatile("ldmatrix.sync.aligned.m8n8.x4.shared.b16 {%0,%1,%2,%3}, [%4];"
        : "=r"(r[0]), "=r"(r[1]), "=r"(r[2]), "=r"(r[3]) : "r"(a));
}
__device__ __forceinline__ void mma16816(float* c, const uint32_t* a, const uint32_t* b){
    asm volatile("mma.sync.aligned.m16n8k16.row.col.f32.bf16.bf16.f32 "
        "{%0,%1,%2,%3}, {%4,%5,%6,%7}, {%8,%9}, {%0,%1,%2,%3};"
        : "+f"(c[0]), "+f"(c[1]), "+f"(c[2]), "+f"(c[3])
        : "r"(a[0]), "r"(a[1]), "r"(a[2]), "r"(a[3]), "r"(b[0]), "r"(b[1]));
}
__device__ __forceinline__ float sigmoidf_(float x){ return 1.0f / (1.0f + __expf(-x)); }
__device__ __forceinline__ uint16_t bf16bits(float v){
    __nv_bfloat16 h = __float2bfloat16(v);
    return *reinterpret_cast<uint16_t*>(&h);
}
__device__ __forceinline__ float bf2f(uint16_t u){
    __nv_bfloat16 h = *reinterpret_cast<__nv_bfloat16*>(&u);
    return __bfloat162float(h);
}
__device__ __forceinline__ void split4(float4 v, uint2& hh, uint2& ll){
    uint16_t h0=bf16bits(v.x), h1=bf16bits(v.y), h2=bf16bits(v.z), h3=bf16bits(v.w);
    uint16_t l0=bf16bits(v.x-bf2f(h0)), l1=bf16bits(v.y-bf2f(h1)),
             l2=bf16bits(v.z-bf2f(h2)), l3=bf16bits(v.w-bf2f(h3));
    hh.x = (uint32_t)h0 | ((uint32_t)h1<<16); hh.y = (uint32_t)h2 | ((uint32_t)h3<<16);
    ll.x = (uint32_t)l0 | ((uint32_t)l1<<16); ll.y = (uint32_t)l2 | ((uint32_t)l3<<16);
}

// Tiles are [rows][128 cols] bf16 with row stride 136 elems = 272 B (16B aligned,
// conflict-free for ldmatrix: 8 rows hit banks 0,4,...,28 with 4 banks each).
#define TSTRIDE 272u

// Split GEMM: C[32 x NTC*32] += (Ah+Al)(Bh+Bl) approx by 3 terms.
// acc[mt(2)][n8(NTC*4)][4].  aHi/aLo/bHi/bLo: smem byte addrs at warp tile origin.
template<int NTC>
__device__ __forceinline__ void gemm_split(float (&acc)[2][NTC*4][4],
    uint32_t aHi, uint32_t aLo, uint32_t bHi, uint32_t bLo, int lane)
{
    const uint32_t aOff = (uint32_t)(lane & 15) * TSTRIDE + (uint32_t)((lane >> 4) << 3) * 2u;
    const uint32_t bOff = (uint32_t)(((lane >> 4) << 3) + (lane & 7)) * TSTRIDE
                        + (uint32_t)(((lane >> 3) & 1) << 3) * 2u;
    for (int ks = 0; ks < 8; ks++) {
        const uint32_t kOff = (uint32_t)ks * 32u;
        uint32_t ah[2][4], al[2][4];
        ldsm_x4(ah[0], aHi + aOff + kOff);
        ldsm_x4(ah[1], aHi + 16u * TSTRIDE + aOff + kOff);
        ldsm_x4(al[0], aLo + aOff + kOff);
        ldsm_x4(al[1], aLo + 16u * TSTRIDE + aOff + kOff);
        #pragma unroll
        for (int nc = 0; nc < NTC; nc++) {
            const uint32_t bb = (uint32_t)nc * 32u * TSTRIDE + bOff + kOff;
            uint32_t bh[2][4], bl[2][4];
            ldsm_x4(bh[0], bHi + bb);
            ldsm_x4(bh[1], bHi + bb + 16u * TSTRIDE);
            ldsm_x4(bl[0], bLo + bb);
            ldsm_x4(bl[1], bLo + bb + 16u * TSTRIDE);
            #pragma unroll
            for (int mt = 0; mt < 2; mt++) {
                #pragma unroll
                for (int q = 0; q < 4; q++) {
                    uint32_t* bhp = &bh[q >> 1][(q & 1) << 1];
                    uint32_t* blp = &bl[q >> 1][(q & 1) << 1];
                    float* c = acc[mt][nc * 4 + q];
                    mma16816(c, ah[mt], bhp);
                    mma16816(c, ah[mt], blp);
                    mma16816(c, al[mt], bhp);
                }
            }
        }
    }
}

// Load fp32 weight W[128][128] into split hi/lo smem tiles.
__device__ __forceinline__ void load_w(char* smp, uint32_t hiOff, uint32_t loOff,
                                       const float* __restrict__ W)
{
    for (int lin = threadIdx.x; lin < 4096; lin += 256) {
        int r = lin >> 5, c4 = (lin & 31) << 2;
        float4 v = *(const float4*)(W + r * 128 + c4);
        uint2 hh, ll;
        split4(v, hh, ll);
        *(uint2*)(smp + hiOff + r * TSTRIDE + c4 * 2) = hh;
        *(uint2*)(smp + loOff + r * TSTRIDE + c4 * 2) = ll;
    }
}

// ============================================================
// Kernel P: LN(z) + 5 projections.  Block = 128 rows, 256 threads (8 warps).
// smem: A_hi 0, A_lo 34816, W0 69632, W1 104448, W2 139264, W3 174080 (208896 B)
// Stage (pair epi) reuses W0/W1.
// ============================================================
#define P_AHI 0u
#define P_ALO 34816u
#define P_W0  69632u
#define P_W1  104448u
#define P_W2  139264u
#define P_W3  174080u
#define P_SMEM 208896

__global__ void __launch_bounds__(256, 1) proj_kernel(
    const float* __restrict__ z, const float* __restrict__ gin, const float* __restrict__ bin,
    const float* __restrict__ wga, const float* __restrict__ bga,
    const float* __restrict__ wpa, const float* __restrict__ bpa,
    const float* __restrict__ wgb, const float* __restrict__ bgb,
    const float* __restrict__ wpb, const float* __restrict__ bpb,
    const float* __restrict__ wog, const float* __restrict__ bog)
{
    extern __shared__ char smp[];
    const uint32_t sb = smem_u32(smp);
    const int tid = threadIdx.x, wid = tid >> 5, lane = tid & 31;

    const size_t m0 = (size_t)blockIdx.x * 128;
    const int b  = (int)(m0 >> 16);
    const int ii = (int)((m0 >> 8) & 255);
    const int k0 = (int)(m0 & 255);

    // ---- LN rows -> split A tiles ----
    uint16_t* aH = (uint16_t*)(smp + P_AHI);
    uint16_t* aL = (uint16_t*)(smp + P_ALO);
    const float gi0 = gin[lane], gi1 = gin[lane+32], gi2 = gin[lane+64], gi3 = gin[lane+96];
    const float bi0 = bin[lane], bi1 = bin[lane+32], bi2 = bin[lane+64], bi3 = bin[lane+96];
    for (int r = 0; r < 16; r++) {
        int row = wid * 16 + r;
        const float* x = z + (m0 + row) * 128;
        float v0 = x[lane], v1 = x[lane+32], v2 = x[lane+64], v3 = x[lane+96];
        float s = v0 + v1 + v2 + v3;
        #pragma unroll
        for (int o = 16; o > 0; o >>= 1) s += __shfl_xor_sync(0xffffffffu, s, o);
        float mean = s * (1.0f / 128.0f);
        float d0 = v0-mean, d1 = v1-mean, d2 = v2-mean, d3 = v3-mean;
        float q = d0*d0 + d1*d1 + d2*d2 + d3*d3;
        #pragma unroll
        for (int o = 16; o > 0; o >>= 1) q += __shfl_xor_sync(0xffffffffu, q, o);
        float inv = rsqrtf(q * (1.0f / 128.0f) + 1e-5f);
        float y0 = d0*inv*gi0 + bi0, y1 = d1*inv*gi1 + bi1;
        float y2 = d2*inv*gi2 + bi2, y3 = d3*inv*gi3 + bi3;
        uint16_t h;
        h = bf16bits(y0); aH[row*136 + lane]      = h; aL[row*136 + lane]      = bf16bits(y0 - bf2f(h));
        h = bf16bits(y1); aH[row*136 + lane + 32] = h; aL[row*136 + lane + 32] = bf16bits(y1 - bf2f(h));
        h = bf16bits(y2); aH[row*136 + lane + 64] = h; aL[row*136 + lane + 64] = bf16bits(y2 - bf2f(h));
        h = bf16bits(y3); aH[row*136 + lane + 96] = h; aL[row*136 + lane + 96] = bf16bits(y3 - bf2f(h));
    }

    const int m0w = (wid & 3) * 32, n0w = (wid >> 2) * 64;
    const uint32_t aHiW = sb + P_AHI + (uint32_t)m0w * TSTRIDE;
    const uint32_t aLoW = sb + P_ALO + (uint32_t)m0w * TSTRIDE;

    // ---- two gated-pair phases ----
    for (int ph = 0; ph < 2; ph++) {
        const float* Wg = ph ? wgb : wga;  const float* bg = ph ? bgb : bga;
        const float* Wp = ph ? wpb : wpa;  const float* bp = ph ? bpb : bpa;
        __syncthreads();                  // stage from prev phase fully consumed
        load_w(smp, P_W0, P_W1, Wg);
        load_w(smp, P_W2, P_W3, Wp);
        __syncthreads();

        float accG[2][8][4] = {}, accP[2][8][4] = {};
        gemm_split<2>(accG, aHiW, aLoW, sb + P_W0 + (uint32_t)n0w * TSTRIDE,
                      sb + P_W1 + (uint32_t)n0w * TSTRIDE, lane);
        gemm_split<2>(accP, aHiW, aLoW, sb + P_W2 + (uint32_t)n0w * TSTRIDE,
                      sb + P_W3 + (uint32_t)n0w * TSTRIDE, lane);
        __syncthreads();                  // all warps done reading W0/W1 before staging

        // stage transposed: stH/stL [n=d 128][m 136] bf16 over W0/W1
        uint16_t* stH = (uint16_t*)(smp + P_W0);
        uint16_t* stL = (uint16_t*)(smp + P_W1);
        #pragma unroll
        for (int mt = 0; mt < 2; mt++)
            #pragma unroll
            for (int n8 = 0; n8 < 8; n8++) {
                int n = n0w + n8 * 8 + 2 * (lane & 3);
                float2 bg2 = *(const float2*)(bg + n);
                float2 bp2 = *(const float2*)(bp + n);
                #pragma unroll
                for (int rh = 0; rh < 2; rh++) {
                    int m = m0w + mt * 16 + (lane >> 2) + rh * 8;
                    float v0 = sigmoidf_(accG[mt][n8][rh*2]   + bg2.x) * (accP[mt][n8][rh*2]   + bp2.x);
                    float v1 = sigmoidf_(accG[mt][n8][rh*2+1] + bg2.y) * (accP[mt][n8][rh*2+1] + bp2.y);
                    uint16_t h0 = bf16bits(v0), h1 = bf16bits(v1);
                    stH[n * 136 + m]       = h0;  stL[n * 136 + m]       = bf16bits(v0 - bf2f(h0));
                    stH[(n + 1) * 136 + m] = h1;  stL[(n + 1) * 136 + m] = bf16bits(v1 - bf2f(h1));
                }
            }
        __syncthreads();

        __nv_bfloat16* dh = ph ? g_bt_hi : g_at_hi;
        __nv_bfloat16* dl = ph ? g_bt_lo : g_at_lo;
        for (int lin = tid; lin < 2048; lin += 256) {
            int d = lin >> 4, m8 = (lin & 15) << 3;
            uint4 vh = *(const uint4*)(smp + P_W0 + d * TSTRIDE + m8 * 2);
            uint4 vl = *(const uint4*)(smp + P_W1 + d * TSTRIDE + m8 * 2);
            size_t gidx = ((size_t)(b * 128 + d)) * 65536 + (size_t)ii * 256 + k0 + m8;
            *(uint4*)(dh + gidx) = vh;
            *(uint4*)(dl + gidx) = vl;
        }
    }

    // ---- gate phase ----
    __syncthreads();
    load_w(smp, P_W0, P_W1, wog);
    __syncthreads();
    float acc[2][8][4] = {};
    gemm_split<2>(acc, aHiW, aLoW, sb + P_W0 + (uint32_t)n0w * TSTRIDE,
                  sb + P_W1 + (uint32_t)n0w * TSTRIDE, lane);
    #pragma unroll
    for (int mt = 0; mt < 2; mt++)
        #pragma unroll
        for (int n8 = 0; n8 < 8; n8++) {
            int n = n0w + n8 * 8 + 2 * (lane & 3);
            float2 bo2 = *(const float2*)(bog + n);
            #pragma unroll
            for (int rh = 0; rh < 2; rh++) {
                int m = m0w + mt * 16 + (lane >> 2) + rh * 8;
                float2 o;
                o.x = sigmoidf_(acc[mt][n8][rh*2]   + bo2.x);
                o.y = sigmoidf_(acc[mt][n8][rh*2+1] + bo2.y);
                *(float2*)(g_gate + (m0 + m) * 128 + n) = o;
            }
        }
}

// ============================================================
// Kernel T: triangle einsum. Block = (bd slice, 128-row i-half), 256 threads.
// C[128 x 256] = A[128 x 256] * B[256 x 256]^T, 2 K-chunks of 128.
// smem: A_hi 0, A_lo 34816, B_hi 69632 (256 rows), B_lo 139264  (208896 B)
// ============================================================
#define T_AHI 0u
#define T_ALO 34816u
#define T_BHI 69632u
#define T_BLO 139264u
#define T_SMEM 208896

__global__ void __launch_bounds__(256, 1) tri_kernel()
{
    extern __shared__ char smp[];
    const uint32_t sb = smem_u32(smp);
    const int tid = threadIdx.x, wid = tid >> 5, lane = tid & 31;
    const int bd = blockIdx.y;
    const int i0 = blockIdx.x * 128;
    const size_t base = (size_t)bd * 65536;

    const int m0w = (wid & 3) * 32, n0w = (wid >> 2) * 128;
    float acc[2][16][4] = {};

    for (int kb = 0; kb < 2; kb++) {
        if (kb) __syncthreads();          // done reading tiles from prev chunk
        for (int lin = tid; lin < 12288; lin += 256) {
            if (lin < 4096) {                 // A hi/lo: 128 rows x 128 k
                int idx = lin & 2047;
                int row = idx >> 4, c8 = (idx & 15) << 3;
                const __nv_bfloat16* s = (lin < 2048) ? g_at_hi : g_at_lo;
                uint32_t dst = (lin < 2048) ? T_AHI : T_ALO;
                uint4 v = *(const uint4*)(s + base + (size_t)(i0 + row) * 256 + kb * 128 + c8);
                *(uint4*)(smp + dst + row * TSTRIDE + c8 * 2) = v;
            } else {                          // B hi/lo: 256 rows x 128 k
                int l2 = lin - 4096;
                int idx = l2 & 4095;
                int row = idx >> 4, c8 = (idx & 15) << 3;
                const __nv_bfloat16* s = (l2 < 4096) ? g_bt_hi : g_bt_lo;
                uint32_t dst = (l2 < 4096) ? T_BHI : T_BLO;
                uint4 v = *(const uint4*)(s + base + (size_t)row * 256 + kb * 128 + c8);
                *(uint4*)(smp + dst + row * TSTRIDE + c8 * 2) = v;
            }
        }
        __syncthreads();
        gemm_split<4>(acc, sb + T_AHI + (uint32_t)m0w * TSTRIDE,
                           sb + T_ALO + (uint32_t)m0w * TSTRIDE,
                           sb + T_BHI + (uint32_t)n0w * TSTRIDE,
                           sb + T_BLO + (uint32_t)n0w * TSTRIDE, lane);
    }

    // epilogue: float2 stores (32B sector-aligned per lane quad)
    #pragma unroll
    for (int mt = 0; mt < 2; mt++)
        #pragma unroll
        for (int n8 = 0; n8 < 16; n8++) {
            int n = n0w + n8 * 8 + 2 * (lane & 3);
            #pragma unroll
            for (int rh = 0; rh < 2; rh++) {
                int m = m0w + mt * 16 + (lane >> 2) + rh * 8;
                float2 o = make_float2(acc[mt][n8][rh*2], acc[mt][n8][rh*2+1]);
                *(float2*)(g_ot + base + (size_t)(i0 + m) * 256 + n) = o;
            }
        }
}

// ============================================================
// Kernel F: transpose-gather + LN + wop + gate.  Block = 128 p-rows, 256 threads.
// smem: X[128][133] f32 @0 (68096), A_hi 68096, A_lo 102912, W_hi 137728, W_lo 172544
// ============================================================
#define F_X   0u
#define F_AHI 68096u
#define F_ALO 102912u
#define F_WHI 137728u
#define F_WLO 172544u
#define F_SMEM 207360

__global__ void __launch_bounds__(256, 1) final_kernel(
    const float* __restrict__ gout, const float* __restrict__ bout,
    const float* __restrict__ wop,  const float* __restrict__ bop,
    float* __restrict__ outp)
{
    extern __shared__ char smp[];
    const uint32_t sb = smem_u32(smp);
    const int tid = threadIdx.x, wid = tid >> 5, lane = tid & 31;
    const int b  = blockIdx.x >> 9;
    const int p0 = (blockIdx.x & 511) * 128;

    // gather-transpose: X[p][d] <- g_ot[b][d][p0+p]
    float* X = (float*)(smp + F_X);
    for (int lin = tid; lin < 16384; lin += 256) {
        int d = lin >> 7, p = lin & 127;
        X[p * 133 + d] = g_ot[((size_t)(b * 128 + d)) * 65536 + p0 + p];
    }
    load_w(smp, F_WHI, F_WLO, wop);
    __syncthreads();

    // LN rows of X -> split A tiles
    uint16_t* aH = (uint16_t*)(smp + F_AHI);
    uint16_t* aL = (uint16_t*)(smp + F_ALO);
    const float go0 = gout[lane], go1 = gout[lane+32], go2 = gout[lane+64], go3 = gout[lane+96];
    const float bo0 = bout[lane], bo1 = bout[lane+32], bo2 = bout[lane+64], bo3 = bout[lane+96];
    for (int r = 0; r < 16; r++) {
        int row = wid * 16 + r;
        const float* x = X + row * 133;
        float v0 = x[lane], v1 = x[lane+32], v2 = x[lane+64], v3 = x[lane+96];
        float s = v0 + v1 + v2 + v3;
        #pragma unroll
        for (int o = 16; o > 0; o >>= 1) s += __shfl_xor_sync(0xffffffffu, s, o);
        float mean = s * (1.0f / 128.0f);
        float d0 = v0-mean, d1 = v1-mean, d2 = v2-mean, d3 = v3-mean;
        float q = d0*d0 + d1*d1 + d2*d2 + d3*d3;
        #pragma unroll
        for (int o = 16; o > 0; o >>= 1) q += __shfl_xor_sync(0xffffffffu, q, o);
        float inv = rsqrtf(q * (1.0f / 128.0f) + 1e-5f);
        float y0 = d0*inv*go0 + bo0, y1 = d1*inv*go1 + bo1;
        float y2 = d2*inv*go2 + bo2, y3 = d3*inv*go3 + bo3;
        uint16_t h;
        h = bf16bits(y0); aH[row*136 + lane]      = h; aL[row*136 + lane]      = bf16bits(y0 - bf2f(h));
        h = bf16bits(y1); aH[row*136 + lane + 32] = h; aL[row*136 + lane + 32] = bf16bits(y1 - bf2f(h));
        h = bf16bits(y2); aH[row*136 + lane + 64] = h; aL[row*136 + lane + 64] = bf16bits(y2 - bf2f(h));
        h = bf16bits(y3); aH[row*136 + lane + 96] = h; aL[row*136 + lane + 96] = bf16bits(y3 - bf2f(h));
    }
    __syncthreads();

    const int m0w = (wid & 3) * 32, n0w = (wid >> 2) * 64;
    float acc[2][8][4] = {};
    gemm_split<2>(acc, sb + F_AHI + (uint32_t)m0w * TSTRIDE,
                       sb + F_ALO + (uint32_t)m0w * TSTRIDE,
                       sb + F_WHI + (uint32_t)n0w * TSTRIDE,
                       sb + F_WLO + (uint32_t)n0w * TSTRIDE, lane);

    // epilogue: (acc + bop) * gate -> out
    #pragma unroll
    for (int mt = 0; mt < 2; mt++)
        #pragma unroll
        for (int n8 = 0; n8 < 8; n8++) {
            int n = n0w + n8 * 8 + 2 * (lane & 3);
            float2 bo2 = *(const float2*)(bop + n);
            #pragma unroll
            for (int rh = 0; rh < 2; rh++) {
                int m = m0w + mt * 16 + (lane >> 2) + rh * 8;
                size_t gi = ((size_t)b * 65536 + p0 + m) * 128 + n;
                float2 g = *(const float2*)(g_gate + gi);
                float2 o;
                o.x = g.x * (acc[mt][n8][rh*2]   + bo2.x);
                o.y = g.y * (acc[mt][n8][rh*2+1] + bo2.y);
                *(float2*)(outp + gi) = o;
            }
        }
}

// ============================================================
// launch
// ============================================================
extern "C" void kernel_launch(void* const* d_in, const int* in_sizes, int n_in,
                              void* d_out, int out_size)
{
    const float* z    = (const float*)d_in[0];
    const float* gin  = (const float*)d_in[1];
    const float* bin  = (const float*)d_in[2];
    const float* wpa  = (const float*)d_in[3];
    const float* bpa  = (const float*)d_in[4];
    const float* wga  = (const float*)d_in[5];
    const float* bga  = (const float*)d_in[6];
    const float* wpb  = (const float*)d_in[7];
    const float* bpb  = (const float*)d_in[8];
    const float* wgb  = (const float*)d_in[9];
    const float* bgb  = (const float*)d_in[10];
    const float* gout = (const float*)d_in[11];
    const float* bout = (const float*)d_in[12];
    const float* wop  = (const float*)d_in[13];
    const float* bop  = (const float*)d_in[14];
    const float* wog  = (const float*)d_in[15];
    const float* bog  = (const float*)d_in[16];
    float* outp = (float*)d_out;

    cudaFuncSetAttribute(proj_kernel,  cudaFuncAttributeMaxDynamicSharedMemorySize, P_SMEM);
    cudaFuncSetAttribute(tri_kernel,   cudaFuncAttributeMaxDynamicSharedMemorySize, T_SMEM);
    cudaFuncSetAttribute(final_kernel, cudaFuncAttributeMaxDynamicSharedMemorySize, F_SMEM);

    proj_kernel<<<2048, 256, P_SMEM>>>(z, gin, bin, wga, bga, wpa, bpa,
                                       wgb, bgb, wpb, bpb, wog, bog);
    tri_kernel<<<dim3(2, 512), 256, T_SMEM>>>();
    final_kernel<<<2048, 256, F_SMEM>>>(gout, bout, wop, bop, outp);
}

// round 4
// speedup vs baseline: 1.9401x; 1.4460x over previous
#include <cuda_runtime.h>
#include <cuda_bf16.h>
#include <stdint.h>

#define ELEMS ((size_t)4*256*256*128)   // 33.5M

// ---------------- scratch ----------------
__device__ __align__(16) __nv_bfloat16 g_at_hi[ELEMS];
__device__ __align__(16) __nv_bfloat16 g_at_lo[ELEMS];
__device__ __align__(16) __nv_bfloat16 g_bt_hi[ELEMS];
__device__ __align__(16) __nv_bfloat16 g_bt_lo[ELEMS];
__device__ __align__(16) float g_gate[ELEMS];
__device__ __align__(16) float g_ot[ELEMS];

// ---------------- helpers ----------------
__device__ __forceinline__ uint32_t smem_u32(const void* p){
    uint32_t a;
    asm("{ .reg .u64 t; cvta.to.shared.u64 t, %1; cvt.u32.u64 %0, t; }" : "=r"(a) : "l"(p));
    return a;
}
__device__ __forceinline__ void ldsm_x4(uint32_t* r, uint32_t a){
    asm volatile("ldmatrix.sync.aligned.m8n8.x4.shared.b16 {%0,%1,%2,%3}, [%4];"
        : "=r"(r[0]), "=r"(r[1]), "=r"(r[2]), "=r"(r[3]) : "r"(a));
}
__device__ __forceinline__ void mma16816(float* c, const uint32_t* a, const uint32_t* b){
    asm volatile("mma.sync.aligned.m16n8k16.row.col.f32.bf16.bf16.f32 "
        "{%0,%1,%2,%3}, {%4,%5,%6,%7}, {%8,%9}, {%0,%1,%2,%3};"
        : "+f"(c[0]), "+f"(c[1]), "+f"(c[2]), "+f"(c[3])
        : "r"(a[0]), "r"(a[1]), "r"(a[2]), "r"(a[3]), "r"(b[0]), "r"(b[1]));
}
__device__ __forceinline__ float sigmoidf_(float x){ return 1.0f / (1.0f + __expf(-x)); }
__device__ __forceinline__ uint16_t bf16bits(float v){
    __nv_bfloat16 h = __float2bfloat16(v);
    return *reinterpret_cast<uint16_t*>(&h);
}
__device__ __forceinline__ float bf2f(uint16_t u){
    __nv_bfloat16 h = *reinterpret_cast<__nv_bfloat16*>(&u);
    return __bfloat162float(h);
}
__device__ __forceinline__ void split4(float4 v, uint2& hh, uint2& ll){
    uint16_t h0=bf16bits(v.x), h1=bf16bits(v.y), h2=bf16bits(v.z), h3=bf16bits(v.w);
    uint16_t l0=bf16bits(v.x-bf2f(h0)), l1=bf16bits(v.y-bf2f(h1)),
             l2=bf16bits(v.z-bf2f(h2)), l3=bf16bits(v.w-bf2f(h3));
    hh.x = (uint32_t)h0 | ((uint32_t)h1<<16); hh.y = (uint32_t)h2 | ((uint32_t)h3<<16);
    ll.x = (uint32_t)l0 | ((uint32_t)l1<<16); ll.y = (uint32_t)l2 | ((uint32_t)l3<<16);
}

#define TSTRIDE 272u   // bf16 tile row stride in bytes (136 elems)

// Split GEMM: C[32 x NTC*32] += 3-term (Ah+Al)(Bh+Bl).
template<int NTC>
__device__ __forceinline__ void gemm_split(float (&acc)[2][NTC*4][4],
    uint32_t aHi, uint32_t aLo, uint32_t bHi, uint32_t bLo, int lane)
{
    const uint32_t aOff = (uint32_t)(lane & 15) * TSTRIDE + (uint32_t)((lane >> 4) << 3) * 2u;
    const uint32_t bOff = (uint32_t)(((lane >> 4) << 3) + (lane & 7)) * TSTRIDE
                        + (uint32_t)(((lane >> 3) & 1) << 3) * 2u;
    #pragma unroll
    for (int ks = 0; ks < 8; ks++) {
        const uint32_t kOff = (uint32_t)ks * 32u;
        uint32_t ah[2][4], al[2][4];
        ldsm_x4(ah[0], aHi + aOff + kOff);
        ldsm_x4(ah[1], aHi + 16u * TSTRIDE + aOff + kOff);
        ldsm_x4(al[0], aLo + aOff + kOff);
        ldsm_x4(al[1], aLo + 16u * TSTRIDE + aOff + kOff);
        #pragma unroll
        for (int nc = 0; nc < NTC; nc++) {
            const uint32_t bb = (uint32_t)nc * 32u * TSTRIDE + bOff + kOff;
            uint32_t bh[2][4], bl[2][4];
            ldsm_x4(bh[0], bHi + bb);
            ldsm_x4(bh[1], bHi + bb + 16u * TSTRIDE);
            ldsm_x4(bl[0], bLo + bb);
            ldsm_x4(bl[1], bLo + bb + 16u * TSTRIDE);
            #pragma unroll
            for (int mt = 0; mt < 2; mt++) {
                #pragma unroll
                for (int q = 0; q < 4; q++) {
                    uint32_t* bhp = &bh[q >> 1][(q & 1) << 1];
                    uint32_t* blp = &bl[q >> 1][(q & 1) << 1];
                    float* c = acc[mt][nc * 4 + q];
                    mma16816(c, ah[mt], bhp);
                    mma16816(c, ah[mt], blp);
                    mma16816(c, al[mt], bhp);
                }
            }
        }
    }
}

// Load fp32 weight W[128][128] into split hi/lo smem tiles. NT = blockDim.
template<int NT>
__device__ __forceinline__ void load_w(char* smp, uint32_t hiOff, uint32_t loOff,
                                       const float* __restrict__ W)
{
    #pragma unroll
    for (int lin = threadIdx.x; lin < 4096; lin += NT) {
        int r = lin >> 5, c4 = (lin & 31) << 2;
        float4 v = *(const float4*)(W + r * 128 + c4);
        uint2 hh, ll;
        split4(v, hh, ll);
        *(uint2*)(smp + hiOff + r * TSTRIDE + c4 * 2) = hh;
        *(uint2*)(smp + loOff + r * TSTRIDE + c4 * 2) = ll;
    }
}

// ============================================================
// Kernel P: LN(z) + 5 projections.  Block = 128 rows, 512 threads (16 warps, 4x4).
// smem: A_hi 0, A_lo 34816, W0 69632, W1 104448, W2 139264, W3 174080 (208896 B)
// ============================================================
#define P_AHI 0u
#define P_ALO 34816u
#define P_W0  69632u
#define P_W1  104448u
#define P_W2  139264u
#define P_W3  174080u
#define P_SMEM 208896

__global__ void __launch_bounds__(512, 1) proj_kernel(
    const float* __restrict__ z, const float* __restrict__ gin, const float* __restrict__ bin,
    const float* __restrict__ wga, const float* __restrict__ bga,
    const float* __restrict__ wpa, const float* __restrict__ bpa,
    const float* __restrict__ wgb, const float* __restrict__ bgb,
    const float* __restrict__ wpb, const float* __restrict__ bpb,
    const float* __restrict__ wog, const float* __restrict__ bog)
{
    extern __shared__ char smp[];
    const uint32_t sb = smem_u32(smp);
    const int tid = threadIdx.x, wid = tid >> 5, lane = tid & 31;

    const size_t m0 = (size_t)blockIdx.x * 128;
    const int b  = (int)(m0 >> 16);
    const int ii = (int)((m0 >> 8) & 255);
    const int k0 = (int)(m0 & 255);

    // ---- LN rows -> split A tiles (8 rows per warp) ----
    uint16_t* aH = (uint16_t*)(smp + P_AHI);
    uint16_t* aL = (uint16_t*)(smp + P_ALO);
    const float gi0 = gin[lane], gi1 = gin[lane+32], gi2 = gin[lane+64], gi3 = gin[lane+96];
    const float bi0 = bin[lane], bi1 = bin[lane+32], bi2 = bin[lane+64], bi3 = bin[lane+96];
    #pragma unroll
    for (int r = 0; r < 8; r++) {
        int row = wid * 8 + r;
        const float* x = z + (m0 + row) * 128;
        float v0 = x[lane], v1 = x[lane+32], v2 = x[lane+64], v3 = x[lane+96];
        float s = v0 + v1 + v2 + v3;
        #pragma unroll
        for (int o = 16; o > 0; o >>= 1) s += __shfl_xor_sync(0xffffffffu, s, o);
        float mean = s * (1.0f / 128.0f);
        float d0 = v0-mean, d1 = v1-mean, d2 = v2-mean, d3 = v3-mean;
        float q = d0*d0 + d1*d1 + d2*d2 + d3*d3;
        #pragma unroll
        for (int o = 16; o > 0; o >>= 1) q += __shfl_xor_sync(0xffffffffu, q, o);
        float inv = rsqrtf(q * (1.0f / 128.0f) + 1e-5f);
        float y0 = d0*inv*gi0 + bi0, y1 = d1*inv*gi1 + bi1;
        float y2 = d2*inv*gi2 + bi2, y3 = d3*inv*gi3 + bi3;
        uint16_t h;
        h = bf16bits(y0); aH[row*136 + lane]      = h; aL[row*136 + lane]      = bf16bits(y0 - bf2f(h));
        h = bf16bits(y1); aH[row*136 + lane + 32] = h; aL[row*136 + lane + 32] = bf16bits(y1 - bf2f(h));
        h = bf16bits(y2); aH[row*136 + lane + 64] = h; aL[row*136 + lane + 64] = bf16bits(y2 - bf2f(h));
        h = bf16bits(y3); aH[row*136 + lane + 96] = h; aL[row*136 + lane + 96] = bf16bits(y3 - bf2f(h));
    }

    const int m0w = (wid >> 2) * 32, n0w = (wid & 3) * 32;
    const uint32_t aHiW = sb + P_AHI + (uint32_t)m0w * TSTRIDE;
    const uint32_t aLoW = sb + P_ALO + (uint32_t)m0w * TSTRIDE;
    const uint32_t nOff = (uint32_t)n0w * TSTRIDE;

    // ---- two gated-pair phases ----
    for (int ph = 0; ph < 2; ph++) {
        const float* Wg = ph ? wgb : wga;  const float* bg = ph ? bgb : bga;
        const float* Wp = ph ? wpb : wpa;  const float* bp = ph ? bpb : bpa;
        __syncthreads();                  // prev stage fully consumed
        load_w<512>(smp, P_W0, P_W1, Wg);
        load_w<512>(smp, P_W2, P_W3, Wp);
        __syncthreads();

        float accG[2][4][4] = {};
        gemm_split<1>(accG, aHiW, aLoW, sb + P_W0 + nOff, sb + P_W1 + nOff, lane);
        float accP[2][4][4] = {};
        gemm_split<1>(accP, aHiW, aLoW, sb + P_W2 + nOff, sb + P_W3 + nOff, lane);
        __syncthreads();                  // all warps done reading W before staging

        // stage transposed: stH/stL [n=d 128][m 136] bf16 over W0/W1
        uint16_t* stH = (uint16_t*)(smp + P_W0);
        uint16_t* stL = (uint16_t*)(smp + P_W1);
        #pragma unroll
        for (int mt = 0; mt < 2; mt++)
            #pragma unroll
            for (int n8 = 0; n8 < 4; n8++) {
                int n = n0w + n8 * 8 + 2 * (lane & 3);
                float2 bg2 = *(const float2*)(bg + n);
                float2 bp2 = *(const float2*)(bp + n);
                #pragma unroll
                for (int rh = 0; rh < 2; rh++) {
                    int m = m0w + mt * 16 + (lane >> 2) + rh * 8;
                    float v0 = sigmoidf_(accG[mt][n8][rh*2]   + bg2.x) * (accP[mt][n8][rh*2]   + bp2.x);
                    float v1 = sigmoidf_(accG[mt][n8][rh*2+1] + bg2.y) * (accP[mt][n8][rh*2+1] + bp2.y);
                    uint16_t h0 = bf16bits(v0), h1 = bf16bits(v1);
                    stH[n * 136 + m]       = h0;  stL[n * 136 + m]       = bf16bits(v0 - bf2f(h0));
                    stH[(n + 1) * 136 + m] = h1;  stL[(n + 1) * 136 + m] = bf16bits(v1 - bf2f(h1));
                }
            }
        __syncthreads();

        __nv_bfloat16* dh = ph ? g_bt_hi : g_at_hi;
        __nv_bfloat16* dl = ph ? g_bt_lo : g_at_lo;
        #pragma unroll
        for (int lin = tid; lin < 2048; lin += 512) {
            int d = lin >> 4, m8 = (lin & 15) << 3;
            uint4 vh = *(const uint4*)(smp + P_W0 + d * TSTRIDE + m8 * 2);
            uint4 vl = *(const uint4*)(smp + P_W1 + d * TSTRIDE + m8 * 2);
            size_t gidx = ((size_t)(b * 128 + d)) * 65536 + (size_t)ii * 256 + k0 + m8;
            *(uint4*)(dh + gidx) = vh;
            *(uint4*)(dl + gidx) = vl;
        }
    }

    // ---- gate phase ----
    __syncthreads();
    load_w<512>(smp, P_W0, P_W1, wog);
    __syncthreads();
    float acc[2][4][4] = {};
    gemm_split<1>(acc, aHiW, aLoW, sb + P_W0 + nOff, sb + P_W1 + nOff, lane);
    #pragma unroll
    for (int mt = 0; mt < 2; mt++)
        #pragma unroll
        for (int n8 = 0; n8 < 4; n8++) {
            int n = n0w + n8 * 8 + 2 * (lane & 3);
            float2 bo2 = *(const float2*)(bog + n);
            #pragma unroll
            for (int rh = 0; rh < 2; rh++) {
                int m = m0w + mt * 16 + (lane >> 2) + rh * 8;
                float2 o;
                o.x = sigmoidf_(acc[mt][n8][rh*2]   + bo2.x);
                o.y = sigmoidf_(acc[mt][n8][rh*2+1] + bo2.y);
                *(float2*)(g_gate + (m0 + m) * 128 + n) = o;
            }
        }
}

// ============================================================
// Kernel T: triangle einsum. Block = (bd, i-half), 512 threads (16 warps 4x4).
// C[128 x 256] = A[128 x 256] * B[256 x 256]^T, 2 K-chunks of 128.
// smem: A_hi 0, A_lo 34816, B_hi 69632 (256 rows), B_lo 139264  (208896 B)
// ============================================================
#define T_AHI 0u
#define T_ALO 34816u
#define T_BHI 69632u
#define T_BLO 139264u
#define T_SMEM 208896

__global__ void __launch_bounds__(512, 1) tri_kernel()
{
    extern __shared__ char smp[];
    const uint32_t sb = smem_u32(smp);
    const int tid = threadIdx.x, wid = tid >> 5, lane = tid & 31;
    const int bd = blockIdx.y;
    const int i0 = blockIdx.x * 128;
    const size_t base = (size_t)bd * 65536;

    const int m0w = (wid >> 2) * 32, n0w = (wid & 3) * 64;
    float acc[2][8][4] = {};

    for (int kb = 0; kb < 2; kb++) {
        if (kb) __syncthreads();
        #pragma unroll
        for (int lin = tid; lin < 12288; lin += 512) {
            if (lin < 4096) {                 // A hi/lo: 128 rows x 128 k
                int idx = lin & 2047;
                int row = idx >> 4, c8 = (idx & 15) << 3;
                const __nv_bfloat16* s = (lin < 2048) ? g_at_hi : g_at_lo;
                uint32_t dst = (lin < 2048) ? T_AHI : T_ALO;
                uint4 v = *(const uint4*)(s + base + (size_t)(i0 + row) * 256 + kb * 128 + c8);
                *(uint4*)(smp + dst + row * TSTRIDE + c8 * 2) = v;
            } else {                          // B hi/lo: 256 rows x 128 k
                int l2 = lin - 4096;
                int idx = l2 & 4095;
                int row = idx >> 4, c8 = (idx & 15) << 3;
                const __nv_bfloat16* s = (l2 < 4096) ? g_bt_hi : g_bt_lo;
                uint32_t dst = (l2 < 4096) ? T_BHI : T_BLO;
                uint4 v = *(const uint4*)(s + base + (size_t)row * 256 + kb * 128 + c8);
                *(uint4*)(smp + dst + row * TSTRIDE + c8 * 2) = v;
            }
        }
        __syncthreads();
        gemm_split<2>(acc, sb + T_AHI + (uint32_t)m0w * TSTRIDE,
                           sb + T_ALO + (uint32_t)m0w * TSTRIDE,
                           sb + T_BHI + (uint32_t)n0w * TSTRIDE,
                           sb + T_BLO + (uint32_t)n0w * TSTRIDE, lane);
    }

    #pragma unroll
    for (int mt = 0; mt < 2; mt++)
        #pragma unroll
        for (int n8 = 0; n8 < 8; n8++) {
            int n = n0w + n8 * 8 + 2 * (lane & 3);
            #pragma unroll
            for (int rh = 0; rh < 2; rh++) {
                int m = m0w + mt * 16 + (lane >> 2) + rh * 8;
                float2 o = make_float2(acc[mt][n8][rh*2], acc[mt][n8][rh*2+1]);
                *(float2*)(g_ot + base + (size_t)(i0 + m) * 256 + n) = o;
            }
        }
}

// ============================================================
// Kernel F: transpose-gather + LN + wop + gate.  512 threads (16 warps 4x4).
// smem: X[128][133] f32 @0 (68096), A_hi 68096, A_lo 102912, W_hi 137728, W_lo 172544
// ============================================================
#define F_X   0u
#define F_AHI 68096u
#define F_ALO 102912u
#define F_WHI 137728u
#define F_WLO 172544u
#define F_SMEM 207360

__global__ void __launch_bounds__(512, 1) final_kernel(
    const float* __restrict__ gout, const float* __restrict__ bout,
    const float* __restrict__ wop,  const float* __restrict__ bop,
    float* __restrict__ outp)
{
    extern __shared__ char smp[];
    const uint32_t sb = smem_u32(smp);
    const int tid = threadIdx.x, wid = tid >> 5, lane = tid & 31;
    const int b  = blockIdx.x >> 9;
    const int p0 = (blockIdx.x & 511) * 128;

    // gather-transpose: X[p][d] <- g_ot[b][d][p0+p]
    float* X = (float*)(smp + F_X);
    #pragma unroll
    for (int lin = tid; lin < 16384; lin += 512) {
        int d = lin >> 7, p = lin & 127;
        X[p * 133 + d] = g_ot[((size_t)(b * 128 + d)) * 65536 + p0 + p];
    }
    load_w<512>(smp, F_WHI, F_WLO, wop);
    __syncthreads();

    // LN rows of X -> split A tiles (8 rows per warp)
    uint16_t* aH = (uint16_t*)(smp + F_AHI);
    uint16_t* aL = (uint16_t*)(smp + F_ALO);
    const float go0 = gout[lane], go1 = gout[lane+32], go2 = gout[lane+64], go3 = gout[lane+96];
    const float bo0 = bout[lane], bo1 = bout[lane+32], bo2 = bout[lane+64], bo3 = bout[lane+96];
    #pragma unroll
    for (int r = 0; r < 8; r++) {
        int row = wid * 8 + r;
        const float* x = X + row * 133;
        float v0 = x[lane], v1 = x[lane+32], v2 = x[lane+64], v3 = x[lane+96];
        float s = v0 + v1 + v2 + v3;
        #pragma unroll
        for (int o = 16; o > 0; o >>= 1) s += __shfl_xor_sync(0xffffffffu, s, o);
        float mean = s * (1.0f / 128.0f);
        float d0 = v0-mean, d1 = v1-mean, d2 = v2-mean, d3 = v3-mean;
        float q = d0*d0 + d1*d1 + d2*d2 + d3*d3;
        #pragma unroll
        for (int o = 16; o > 0; o >>= 1) q += __shfl_xor_sync(0xffffffffu, q, o);
        float inv = rsqrtf(q * (1.0f / 128.0f) + 1e-5f);
        float y0 = d0*inv*go0 + bo0, y1 = d1*inv*go1 + bo1;
        float y2 = d2*inv*go2 + bo2, y3 = d3*inv*go3 + bo3;
        uint16_t h;
        h = bf16bits(y0); aH[row*136 + lane]      = h; aL[row*136 + lane]      = bf16bits(y0 - bf2f(h));
        h = bf16bits(y1); aH[row*136 + lane + 32] = h; aL[row*136 + lane + 32] = bf16bits(y1 - bf2f(h));
        h = bf16bits(y2); aH[row*136 + lane + 64] = h; aL[row*136 + lane + 64] = bf16bits(y2 - bf2f(h));
        h = bf16bits(y3); aH[row*136 + lane + 96] = h; aL[row*136 + lane + 96] = bf16bits(y3 - bf2f(h));
    }
    __syncthreads();

    const int m0w = (wid >> 2) * 32, n0w = (wid & 3) * 32;
    float acc[2][4][4] = {};
    gemm_split<1>(acc, sb + F_AHI + (uint32_t)m0w * TSTRIDE,
                       sb + F_ALO + (uint32_t)m0w * TSTRIDE,
                       sb + F_WHI + (uint32_t)n0w * TSTRIDE,
                       sb + F_WLO + (uint32_t)n0w * TSTRIDE, lane);

    #pragma unroll
    for (int mt = 0; mt < 2; mt++)
        #pragma unroll
        for (int n8 = 0; n8 < 4; n8++) {
            int n = n0w + n8 * 8 + 2 * (lane & 3);
            float2 bo2 = *(const float2*)(bop + n);
            #pragma unroll
            for (int rh = 0; rh < 2; rh++) {
                int m = m0w + mt * 16 + (lane >> 2) + rh * 8;
                size_t gi = ((size_t)b * 65536 + p0 + m) * 128 + n;
                float2 g = *(const float2*)(g_gate + gi);
                float2 o;
                o.x = g.x * (acc[mt][n8][rh*2]   + bo2.x);
                o.y = g.y * (acc[mt][n8][rh*2+1] + bo2.y);
                *(float2*)(outp + gi) = o;
            }
        }
}

// ============================================================
// launch
// ============================================================
extern "C" void kernel_launch(void* const* d_in, const int* in_sizes, int n_in,
                              void* d_out, int out_size)
{
    const float* z    = (const float*)d_in[0];
    const float* gin  = (const float*)d_in[1];
    const float* bin  = (const float*)d_in[2];
    const float* wpa  = (const float*)d_in[3];
    const float* bpa  = (const float*)d_in[4];
    const float* wga  = (const float*)d_in[5];
    const float* bga  = (const float*)d_in[6];
    const float* wpb  = (const float*)d_in[7];
    const float* bpb  = (const float*)d_in[8];
    const float* wgb  = (const float*)d_in[9];
    const float* bgb  = (const float*)d_in[10];
    const float* gout = (const float*)d_in[11];
    const float* bout = (const float*)d_in[12];
    const float* wop  = (const float*)d_in[13];
    const float* bop  = (const float*)d_in[14];
    const float* wog  = (const float*)d_in[15];
    const float* bog  = (const float*)d_in[16];
    float* outp = (float*)d_out;

    cudaFuncSetAttribute(proj_kernel,  cudaFuncAttributeMaxDynamicSharedMemorySize, P_SMEM);
    cudaFuncSetAttribute(tri_kernel,   cudaFuncAttributeMaxDynamicSharedMemorySize, T_SMEM);
    cudaFuncSetAttribute(final_kernel, cudaFuncAttributeMaxDynamicSharedMemorySize, F_SMEM);

    proj_kernel<<<2048, 512, P_SMEM>>>(z, gin, bin, wga, bga, wpa, bpa,
                                       wgb, bgb, wpb, bpb, wog, bog);
    tri_kernel<<<dim3(2, 512), 512, T_SMEM>>>();
    final_kernel<<<2048, 512, F_SMEM>>>(gout, bout, wop, bop, outp);
}

// round 5
// speedup vs baseline: 2.4040x; 1.2391x over previous
#include <cuda_runtime.h>
#include <cuda_bf16.h>
#include <stdint.h>

#define ELEMS ((size_t)4*256*256*128)   // 33.5M

// ---------------- scratch ----------------
__device__ __align__(16) __nv_bfloat16 g_at_hi[ELEMS];
__device__ __align__(16) __nv_bfloat16 g_at_lo[ELEMS];
__device__ __align__(16) __nv_bfloat16 g_bt_hi[ELEMS];
__device__ __align__(16) __nv_bfloat16 g_bt_lo[ELEMS];
__device__ __align__(16) float g_gate[ELEMS];
__device__ __align__(16) float g_ot[ELEMS];

// ---------------- helpers ----------------
__device__ __forceinline__ uint32_t smem_u32(const void* p){
    uint32_t a;
    asm("{ .reg .u64 t; cvta.to.shared.u64 t, %1; cvt.u32.u64 %0, t; }" : "=r"(a) : "l"(p));
    return a;
}
__device__ __forceinline__ void ldsm_x4(uint32_t* r, uint32_t a){
    asm volatile("ldmatrix.sync.aligned.m8n8.x4.shared.b16 {%0,%1,%2,%3}, [%4];"
        : "=r"(r[0]), "=r"(r[1]), "=r"(r[2]), "=r"(r[3]) : "r"(a));
}
__device__ __forceinline__ void mma16816(float* c, const uint32_t* a, const uint32_t* b){
    asm volatile("mma.sync.aligned.m16n8k16.row.col.f32.bf16.bf16.f32 "
        "{%0,%1,%2,%3}, {%4,%5,%6,%7}, {%8,%9}, {%0,%1,%2,%3};"
        : "+f"(c[0]), "+f"(c[1]), "+f"(c[2]), "+f"(c[3])
        : "r"(a[0]), "r"(a[1]), "r"(a[2]), "r"(a[3]), "r"(b[0]), "r"(b[1]));
}
__device__ __forceinline__ float sigmoidf_(float x){ return 1.0f / (1.0f + __expf(-x)); }
__device__ __forceinline__ uint16_t bf16bits(float v){
    __nv_bfloat16 h = __float2bfloat16(v);
    return *reinterpret_cast<uint16_t*>(&h);
}
__device__ __forceinline__ float bf2f(uint16_t u){
    __nv_bfloat16 h = *reinterpret_cast<__nv_bfloat16*>(&u);
    return __bfloat162float(h);
}
__device__ __forceinline__ void split4(float4 v, uint2& hh, uint2& ll){
    uint16_t h0=bf16bits(v.x), h1=bf16bits(v.y), h2=bf16bits(v.z), h3=bf16bits(v.w);
    uint16_t l0=bf16bits(v.x-bf2f(h0)), l1=bf16bits(v.y-bf2f(h1)),
             l2=bf16bits(v.z-bf2f(h2)), l3=bf16bits(v.w-bf2f(h3));
    hh.x = (uint32_t)h0 | ((uint32_t)h1<<16); hh.y = (uint32_t)h2 | ((uint32_t)h3<<16);
    ll.x = (uint32_t)l0 | ((uint32_t)l1<<16); ll.y = (uint32_t)l2 | ((uint32_t)l3<<16);
}

#define TSTRIDE 272u   // bf16 tile row stride in bytes (136 elems)

// 16x32 warp-tile split GEMM: acc[4 n-octets][4], 3-term (Ah+Al)(Bh+Bl).
template<int KS>
__device__ __forceinline__ void gemm16x32(float (&acc)[4][4],
    uint32_t aHi, uint32_t aLo, uint32_t bHi, uint32_t bLo, int lane)
{
    const uint32_t aOff = (uint32_t)(lane & 15) * TSTRIDE + (uint32_t)((lane >> 4) << 4);
    const uint32_t bOff = (uint32_t)(((lane >> 4) << 3) + (lane & 7)) * TSTRIDE
                        + (uint32_t)(((lane >> 3) & 1) << 4);
    #pragma unroll
    for (int ks = 0; ks < KS; ks++) {
        const uint32_t kOff = (uint32_t)ks * 32u;
        uint32_t ah[4], al[4];
        ldsm_x4(ah, aHi + aOff + kOff);
        ldsm_x4(al, aLo + aOff + kOff);
        uint32_t bh[2][4], bl[2][4];
        ldsm_x4(bh[0], bHi + bOff + kOff);
        ldsm_x4(bh[1], bHi + bOff + kOff + 16u * TSTRIDE);
        ldsm_x4(bl[0], bLo + bOff + kOff);
        ldsm_x4(bl[1], bLo + bOff + kOff + 16u * TSTRIDE);
        #pragma unroll
        for (int q = 0; q < 4; q++) {
            uint32_t* bhp = &bh[q >> 1][(q & 1) << 1];
            uint32_t* blp = &bl[q >> 1][(q & 1) << 1];
            mma16816(acc[q], ah, bhp);
            mma16816(acc[q], ah, blp);
            mma16816(acc[q], al, bhp);
        }
    }
}

// Load fp32 weight W[128][128] into split hi/lo smem tiles (272B row stride).
__device__ __forceinline__ void load_w(char* smp, uint32_t hiOff, uint32_t loOff,
                                       const float* __restrict__ W)
{
    #pragma unroll
    for (int it = 0; it < 8; it++) {
        int lin = threadIdx.x + it * 512;
        int r = lin >> 5, c4 = (lin & 31) << 2;
        float4 v = *(const float4*)(W + r * 128 + c4);
        uint2 hh, ll;
        split4(v, hh, ll);
        *(uint2*)(smp + hiOff + r * TSTRIDE + c4 * 2) = hh;
        *(uint2*)(smp + loOff + r * TSTRIDE + c4 * 2) = ll;
    }
}

// LN one row (over 128 cols) by a full warp; write split bf16 into A tile.
__device__ __forceinline__ void ln_row(char* smp, uint32_t hiOff, uint32_t loOff,
    int row, int lane, const float* x,
    float g0, float g1, float g2, float g3,
    float c0, float c1, float c2, float c3)
{
    float v0 = x[lane], v1 = x[lane+32], v2 = x[lane+64], v3 = x[lane+96];
    float s = v0 + v1 + v2 + v3;
    #pragma unroll
    for (int o = 16; o > 0; o >>= 1) s += __shfl_xor_sync(0xffffffffu, s, o);
    float mean = s * (1.0f / 128.0f);
    float d0 = v0-mean, d1 = v1-mean, d2 = v2-mean, d3 = v3-mean;
    float q = d0*d0 + d1*d1 + d2*d2 + d3*d3;
    #pragma unroll
    for (int o = 16; o > 0; o >>= 1) q += __shfl_xor_sync(0xffffffffu, q, o);
    float inv = rsqrtf(q * (1.0f / 128.0f) + 1e-5f);
    float y0 = d0*inv*g0 + c0, y1 = d1*inv*g1 + c1;
    float y2 = d2*inv*g2 + c2, y3 = d3*inv*g3 + c3;
    uint16_t* aH = (uint16_t*)(smp + hiOff);
    uint16_t* aL = (uint16_t*)(smp + loOff);
    uint16_t h;
    h = bf16bits(y0); aH[row*136 + lane]      = h; aL[row*136 + lane]      = bf16bits(y0 - bf2f(h));
    h = bf16bits(y1); aH[row*136 + lane + 32] = h; aL[row*136 + lane + 32] = bf16bits(y1 - bf2f(h));
    h = bf16bits(y2); aH[row*136 + lane + 64] = h; aL[row*136 + lane + 64] = bf16bits(y2 - bf2f(h));
    h = bf16bits(y3); aH[row*136 + lane + 96] = h; aL[row*136 + lane + 96] = bf16bits(y3 - bf2f(h));
}

// ============================================================
// Kernel P: LN(z) + 5 projections.  Block = 64 rows, 512 threads, 2 CTAs/SM.
// smem: A_hi 0 (17408), A_lo 17408, W_hi 34816 (34816), W_lo 69632  = 104448
// Stage (pair epilogue) overlays W: stH @34816, stL @53248 (128 x 72 elems).
// ============================================================
#define PR_AHI 0u
#define PR_ALO 17408u
#define PR_WHI 34816u
#define PR_WLO 69632u
#define PR_STH 34816u
#define PR_STL 53248u
#define PR_SMEM 104448

__global__ void __launch_bounds__(512, 2) proj_kernel(
    const float* __restrict__ z, const float* __restrict__ gin, const float* __restrict__ bin,
    const float* __restrict__ wga, const float* __restrict__ bga,
    const float* __restrict__ wpa, const float* __restrict__ bpa,
    const float* __restrict__ wgb, const float* __restrict__ bgb,
    const float* __restrict__ wpb, const float* __restrict__ bpb,
    const float* __restrict__ wog, const float* __restrict__ bog)
{
    extern __shared__ char smp[];
    const uint32_t sb = smem_u32(smp);
    const int tid = threadIdx.x, wid = tid >> 5, lane = tid & 31;

    const size_t m0 = (size_t)blockIdx.x * 64;
    const int b  = (int)(m0 >> 16);
    const int ii = (int)((m0 >> 8) & 255);
    const int k0 = (int)(m0 & 255);

    // ---- LN rows -> split A tiles (4 rows per warp) ----
    {
        const float g0 = gin[lane], g1 = gin[lane+32], g2 = gin[lane+64], g3 = gin[lane+96];
        const float c0 = bin[lane], c1 = bin[lane+32], c2 = bin[lane+64], c3 = bin[lane+96];
        #pragma unroll
        for (int r = 0; r < 4; r++) {
            int row = wid * 4 + r;
            ln_row(smp, PR_AHI, PR_ALO, row, lane, z + (m0 + row) * 128,
                   g0, g1, g2, g3, c0, c1, c2, c3);
        }
    }

    const int m0w = (wid >> 2) * 16, n0w = (wid & 3) * 32;
    const uint32_t aHiW = sb + PR_AHI + (uint32_t)m0w * TSTRIDE;
    const uint32_t aLoW = sb + PR_ALO + (uint32_t)m0w * TSTRIDE;
    const uint32_t nOff = (uint32_t)n0w * TSTRIDE;

    // ---- two gated-pair phases ----
    for (int ph = 0; ph < 2; ph++) {
        const float* Wg = ph ? wgb : wga;  const float* bg = ph ? bgb : bga;
        const float* Wp = ph ? wpb : wpa;  const float* bp = ph ? bpb : bpa;

        __syncthreads();
        load_w(smp, PR_WHI, PR_WLO, Wg);
        __syncthreads();
        float accG[4][4] = {};
        gemm16x32<8>(accG, aHiW, aLoW, sb + PR_WHI + nOff, sb + PR_WLO + nOff, lane);

        __syncthreads();
        load_w(smp, PR_WHI, PR_WLO, Wp);
        __syncthreads();
        float accP[4][4] = {};
        gemm16x32<8>(accP, aHiW, aLoW, sb + PR_WHI + nOff, sb + PR_WLO + nOff, lane);
        __syncthreads();

        // stage transposed: stH/stL [d 128][m 72] bf16 over W region
        uint16_t* stH = (uint16_t*)(smp + PR_STH);
        uint16_t* stL = (uint16_t*)(smp + PR_STL);
        #pragma unroll
        for (int q = 0; q < 4; q++) {
            int n = n0w + q * 8 + 2 * (lane & 3);
            float2 bg2 = *(const float2*)(bg + n);
            float2 bp2 = *(const float2*)(bp + n);
            #pragma unroll
            for (int rh = 0; rh < 2; rh++) {
                int m = m0w + (lane >> 2) + rh * 8;
                float v0 = sigmoidf_(accG[q][rh*2]   + bg2.x) * (accP[q][rh*2]   + bp2.x);
                float v1 = sigmoidf_(accG[q][rh*2+1] + bg2.y) * (accP[q][rh*2+1] + bp2.y);
                uint16_t h0 = bf16bits(v0), h1 = bf16bits(v1);
                stH[n * 72 + m]       = h0;  stL[n * 72 + m]       = bf16bits(v0 - bf2f(h0));
                stH[(n + 1) * 72 + m] = h1;  stL[(n + 1) * 72 + m] = bf16bits(v1 - bf2f(h1));
            }
        }
        __syncthreads();

        __nv_bfloat16* dH = ph ? g_bt_hi : g_at_hi;
        __nv_bfloat16* dL = ph ? g_bt_lo : g_at_lo;
        #pragma unroll
        for (int it = 0; it < 4; it++) {
            int lin = tid + it * 512;          // 0..2047
            int hl  = lin >> 10;
            int idx = lin & 1023;
            int d = idx >> 3, m8 = (idx & 7) << 3;
            uint4 v = *(const uint4*)(smp + (hl ? PR_STL : PR_STH) + d * 144 + m8 * 2);
            __nv_bfloat16* dst = hl ? dL : dH;
            *(uint4*)(dst + ((size_t)(b * 128 + d)) * 65536 + (size_t)ii * 256 + k0 + m8) = v;
        }
    }

    // ---- gate phase ----
    __syncthreads();
    load_w(smp, PR_WHI, PR_WLO, wog);
    __syncthreads();
    float acc[4][4] = {};
    gemm16x32<8>(acc, aHiW, aLoW, sb + PR_WHI + nOff, sb + PR_WLO + nOff, lane);
    #pragma unroll
    for (int q = 0; q < 4; q++) {
        int n = n0w + q * 8 + 2 * (lane & 3);
        float2 bo2 = *(const float2*)(bog + n);
        #pragma unroll
        for (int rh = 0; rh < 2; rh++) {
            int m = m0w + (lane >> 2) + rh * 8;
            float2 o;
            o.x = sigmoidf_(acc[q][rh*2]   + bo2.x);
            o.y = sigmoidf_(acc[q][rh*2+1] + bo2.y);
            *(float2*)(g_gate + (m0 + m) * 128 + n) = o;
        }
    }
}

// ============================================================
// Kernel T: triangle einsum. C tile 64x128 per block, 512 threads, 2 CTAs/SM.
// K = 256 in 2 chunks of 128.  smem: A_hi 0, A_lo 17408, B_hi 34816, B_lo 69632.
// grid.x = 4096: bd = bx>>3, i0 = ((bx>>1)&3)*64, j0 = (bx&1)*128
// ============================================================
#define TR_AHI 0u
#define TR_ALO 17408u
#define TR_BHI 34816u
#define TR_BLO 69632u
#define TR_SMEM 104448

__global__ void __launch_bounds__(512, 2) tri_kernel()
{
    extern __shared__ char smp[];
    const uint32_t sb = smem_u32(smp);
    const int tid = threadIdx.x, wid = tid >> 5, lane = tid & 31;
    const int bx = blockIdx.x;
    const int bd = bx >> 3;
    const int i0 = ((bx >> 1) & 3) * 64;
    const int j0 = (bx & 1) * 128;
    const size_t base = (size_t)bd * 65536;

    const int m0w = (wid >> 2) * 16, n0w = (wid & 3) * 32;
    float acc[4][4] = {};

    for (int kb = 0; kb < 2; kb++) {
        if (kb) __syncthreads();
        #pragma unroll
        for (int it = 0; it < 12; it++) {
            int lin = tid + it * 512;          // 0..6143
            if (lin < 2048) {                  // A: 64 rows x 128 k, hi then lo
                int idx = lin & 1023;
                int row = idx >> 4, c8 = (idx & 15) << 3;
                const __nv_bfloat16* s = (lin < 1024) ? g_at_hi : g_at_lo;
                uint32_t dst = (lin < 1024) ? TR_AHI : TR_ALO;
                uint4 v = *(const uint4*)(s + base + (size_t)(i0 + row) * 256 + kb * 128 + c8);
                *(uint4*)(smp + dst + row * TSTRIDE + c8 * 2) = v;
            } else {                           // B: 128 rows x 128 k, hi then lo
                int l2 = lin - 2048;
                int idx = l2 & 2047;
                int row = idx >> 4, c8 = (idx & 15) << 3;
                const __nv_bfloat16* s = (l2 < 2048) ? g_bt_hi : g_bt_lo;
                uint32_t dst = (l2 < 2048) ? TR_BHI : TR_BLO;
                uint4 v = *(const uint4*)(s + base + (size_t)(j0 + row) * 256 + kb * 128 + c8);
                *(uint4*)(smp + dst + row * TSTRIDE + c8 * 2) = v;
            }
        }
        __syncthreads();
        gemm16x32<8>(acc, sb + TR_AHI + (uint32_t)m0w * TSTRIDE,
                          sb + TR_ALO + (uint32_t)m0w * TSTRIDE,
                          sb + TR_BHI + (uint32_t)n0w * TSTRIDE,
                          sb + TR_BLO + (uint32_t)n0w * TSTRIDE, lane);
    }

    #pragma unroll
    for (int q = 0; q < 4; q++) {
        int n = n0w + q * 8 + 2 * (lane & 3);
        #pragma unroll
        for (int rh = 0; rh < 2; rh++) {
            int m = m0w + (lane >> 2) + rh * 8;
            float2 o = make_float2(acc[q][rh*2], acc[q][rh*2+1]);
            *(float2*)(g_ot + base + (size_t)(i0 + m) * 256 + j0 + n) = o;
        }
    }
}

// ============================================================
// Kernel F: transpose-gather + LN + wop + gate.  64 p-rows, 512 threads, 2 CTAs/SM.
// smem: A_hi 0, A_lo 17408; X f32 [64][133] @34816 (34048, dead after LN);
//       W_hi 34816, W_lo 69632 (overlays X).  Total 104448.
// grid.x = 4096: b = bx>>10, p0 = (bx&1023)*64
// ============================================================
#define FN_AHI 0u
#define FN_ALO 17408u
#define FN_X   34816u
#define FN_WHI 34816u
#define FN_WLO 69632u
#define FN_SMEM 104448

__global__ void __launch_bounds__(512, 2) final_kernel(
    const float* __restrict__ gout, const float* __restrict__ bout,
    const float* __restrict__ wop,  const float* __restrict__ bop,
    float* __restrict__ outp)
{
    extern __shared__ char smp[];
    const uint32_t sb = smem_u32(smp);
    const int tid = threadIdx.x, wid = tid >> 5, lane = tid & 31;
    const int b  = blockIdx.x >> 10;
    const int p0 = (blockIdx.x & 1023) * 64;

    // gather-transpose: X[p][d] <- g_ot[b][d][p0+p]   (2048 float4 reads)
    float* X = (float*)(smp + FN_X);
    #pragma unroll
    for (int it = 0; it < 4; it++) {
        int lin = tid + it * 512;
        int d = lin >> 4, p4 = (lin & 15) << 2;
        float4 v = *(const float4*)(g_ot + ((size_t)(b * 128 + d)) * 65536 + p0 + p4);
        X[(p4 + 0) * 133 + d] = v.x;
        X[(p4 + 1) * 133 + d] = v.y;
        X[(p4 + 2) * 133 + d] = v.z;
        X[(p4 + 3) * 133 + d] = v.w;
    }
    __syncthreads();

    // LN rows of X -> split A tiles (4 rows per warp)
    {
        const float g0 = gout[lane], g1 = gout[lane+32], g2 = gout[lane+64], g3 = gout[lane+96];
        const float c0 = bout[lane], c1 = bout[lane+32], c2 = bout[lane+64], c3 = bout[lane+96];
        #pragma unroll
        for (int r = 0; r < 4; r++) {
            int row = wid * 4 + r;
            ln_row(smp, FN_AHI, FN_ALO, row, lane, X + row * 133,
                   g0, g1, g2, g3, c0, c1, c2, c3);
        }
    }
    __syncthreads();            // X fully consumed before W overlays it
    load_w(smp, FN_WHI, FN_WLO, wop);
    __syncthreads();

    const int m0w = (wid >> 2) * 16, n0w = (wid & 3) * 32;
    float acc[4][4] = {};
    gemm16x32<8>(acc, sb + FN_AHI + (uint32_t)m0w * TSTRIDE,
                      sb + FN_ALO + (uint32_t)m0w * TSTRIDE,
                      sb + FN_WHI + (uint32_t)n0w * TSTRIDE,
                      sb + FN_WLO + (uint32_t)n0w * TSTRIDE, lane);

    #pragma unroll
    for (int q = 0; q < 4; q++) {
        int n = n0w + q * 8 + 2 * (lane & 3);
        float2 bo2 = *(const float2*)(bop + n);
        #pragma unroll
        for (int rh = 0; rh < 2; rh++) {
            int m = m0w + (lane >> 2) + rh * 8;
            size_t gi = ((size_t)b * 65536 + p0 + m) * 128 + n;
            float2 g = *(const float2*)(g_gate + gi);
            float2 o;
            o.x = g.x * (acc[q][rh*2]   + bo2.x);
            o.y = g.y * (acc[q][rh*2+1] + bo2.y);
            *(float2*)(outp + gi) = o;
        }
    }
}

// ============================================================
// launch
// ============================================================
extern "C" void kernel_launch(void* const* d_in, const int* in_sizes, int n_in,
                              void* d_out, int out_size)
{
    const float* z    = (const float*)d_in[0];
    const float* gin  = (const float*)d_in[1];
    const float* bin  = (const float*)d_in[2];
    const float* wpa  = (const float*)d_in[3];
    const float* bpa  = (const float*)d_in[4];
    const float* wga  = (const float*)d_in[5];
    const float* bga  = (const float*)d_in[6];
    const float* wpb  = (const float*)d_in[7];
    const float* bpb  = (const float*)d_in[8];
    const float* wgb  = (const float*)d_in[9];
    const float* bgb  = (const float*)d_in[10];
    const float* gout = (const float*)d_in[11];
    const float* bout = (const float*)d_in[12];
    const float* wop  = (const float*)d_in[13];
    const float* bop  = (const float*)d_in[14];
    const float* wog  = (const float*)d_in[15];
    const float* bog  = (const float*)d_in[16];
    float* outp = (float*)d_out;

    cudaFuncSetAttribute(proj_kernel,  cudaFuncAttributeMaxDynamicSharedMemorySize, PR_SMEM);
    cudaFuncSetAttribute(tri_kernel,   cudaFuncAttributeMaxDynamicSharedMemorySize, TR_SMEM);
    cudaFuncSetAttribute(final_kernel, cudaFuncAttributeMaxDynamicSharedMemorySize, FN_SMEM);

    proj_kernel<<<4096, 512, PR_SMEM>>>(z, gin, bin, wga, bga, wpa, bpa,
                                        wgb, bgb, wpb, bpb, wog, bog);
    tri_kernel<<<4096, 512, TR_SMEM>>>();
    final_kernel<<<4096, 512, FN_SMEM>>>(gout, bout, wop, bop, outp);
}

// round 6
// speedup vs baseline: 2.9028x; 1.2075x over previous
#include <cuda_runtime.h>
#include <cuda_bf16.h>
#include <stdint.h>

#define ELEMS ((size_t)4*256*256*128)   // 33.5M

// ---------------- scratch ----------------
__device__ __align__(16) __nv_bfloat16 g_at_hi[ELEMS];
__device__ __align__(16) __nv_bfloat16 g_at_lo[ELEMS];
__device__ __align__(16) __nv_bfloat16 g_bt_hi[ELEMS];
__device__ __align__(16) __nv_bfloat16 g_bt_lo[ELEMS];
__device__ __align__(16) float g_gate[ELEMS];
__device__ __align__(16) float g_ot[ELEMS];
// pre-split weight tile images: 6 mats x (hi 34816 B + lo 34816 B)
__device__ __align__(16) unsigned char g_wt[6 * 69632];

// ---------------- helpers ----------------
__device__ __forceinline__ uint32_t smem_u32(const void* p){
    uint32_t a;
    asm("{ .reg .u64 t; cvta.to.shared.u64 t, %1; cvt.u32.u64 %0, t; }" : "=r"(a) : "l"(p));
    return a;
}
__device__ __forceinline__ void ldsm_x4(uint32_t* r, uint32_t a){
    asm volatile("ldmatrix.sync.aligned.m8n8.x4.shared.b16 {%0,%1,%2,%3}, [%4];"
        : "=r"(r[0]), "=r"(r[1]), "=r"(r[2]), "=r"(r[3]) : "r"(a));
}
__device__ __forceinline__ void mma16816(float* c, const uint32_t* a, const uint32_t* b){
    asm volatile("mma.sync.aligned.m16n8k16.row.col.f32.bf16.bf16.f32 "
        "{%0,%1,%2,%3}, {%4,%5,%6,%7}, {%8,%9}, {%0,%1,%2,%3};"
        : "+f"(c[0]), "+f"(c[1]), "+f"(c[2]), "+f"(c[3])
        : "r"(a[0]), "r"(a[1]), "r"(a[2]), "r"(a[3]), "r"(b[0]), "r"(b[1]));
}
__device__ __forceinline__ void cp16(uint32_t dst, const void* src){
    asm volatile("cp.async.cg.shared.global [%0], [%1], 16;" :: "r"(dst), "l"(src));
}
__device__ __forceinline__ void cp_commit(){
    asm volatile("cp.async.commit_group;" ::: "memory");
}
__device__ __forceinline__ void cp_wait_all(){
    asm volatile("cp.async.wait_group 0;" ::: "memory");
}
__device__ __forceinline__ float sigmoidf_(float x){ return 1.0f / (1.0f + __expf(-x)); }
__device__ __forceinline__ uint16_t bf16bits(float v){
    __nv_bfloat16 h = __float2bfloat16(v);
    return *reinterpret_cast<uint16_t*>(&h);
}
__device__ __forceinline__ float bf2f(uint16_t u){
    __nv_bfloat16 h = *reinterpret_cast<__nv_bfloat16*>(&u);
    return __bfloat162float(h);
}
__device__ __forceinline__ void split4(float4 v, uint2& hh, uint2& ll){
    uint16_t h0=bf16bits(v.x), h1=bf16bits(v.y), h2=bf16bits(v.z), h3=bf16bits(v.w);
    uint16_t l0=bf16bits(v.x-bf2f(h0)), l1=bf16bits(v.y-bf2f(h1)),
             l2=bf16bits(v.z-bf2f(h2)), l3=bf16bits(v.w-bf2f(h3));
    hh.x = (uint32_t)h0 | ((uint32_t)h1<<16); hh.y = (uint32_t)h2 | ((uint32_t)h3<<16);
    ll.x = (uint32_t)l0 | ((uint32_t)l1<<16); ll.y = (uint32_t)l2 | ((uint32_t)l3<<16);
}

#define TSTRIDE 272u   // bf16 tile row stride in bytes (136 elems)

// 16x32 warp-tile split GEMM: acc[4 n-octets][4], 3-term (Ah+Al)(Bh+Bl).
template<int KS>
__device__ __forceinline__ void gemm16x32(float (&acc)[4][4],
    uint32_t aHi, uint32_t aLo, uint32_t bHi, uint32_t bLo, int lane)
{
    const uint32_t aOff = (uint32_t)(lane & 15) * TSTRIDE + (uint32_t)((lane >> 4) << 4);
    const uint32_t bOff = (uint32_t)(((lane >> 4) << 3) + (lane & 7)) * TSTRIDE
                        + (uint32_t)(((lane >> 3) & 1) << 4);
    #pragma unroll
    for (int ks = 0; ks < KS; ks++) {
        const uint32_t kOff = (uint32_t)ks * 32u;
        uint32_t ah[4], al[4];
        ldsm_x4(ah, aHi + aOff + kOff);
        ldsm_x4(al, aLo + aOff + kOff);
        uint32_t bh[2][4], bl[2][4];
        ldsm_x4(bh[0], bHi + bOff + kOff);
        ldsm_x4(bh[1], bHi + bOff + kOff + 16u * TSTRIDE);
        ldsm_x4(bl[0], bLo + bOff + kOff);
        ldsm_x4(bl[1], bLo + bOff + kOff + 16u * TSTRIDE);
        #pragma unroll
        for (int q = 0; q < 4; q++) {
            uint32_t* bhp = &bh[q >> 1][(q & 1) << 1];
            uint32_t* blp = &bl[q >> 1][(q & 1) << 1];
            mma16816(acc[q], ah, bhp);
            mma16816(acc[q], ah, blp);
            mma16816(acc[q], al, bhp);
        }
    }
}

// async copy one pre-split weight tile image (69632 B) into smem
__device__ __forceinline__ void load_w_async(uint32_t smemDst, int mat){
    const unsigned char* src = g_wt + (size_t)mat * 69632;
    for (int lin = threadIdx.x; lin < 4352; lin += 512)
        cp16(smemDst + (uint32_t)lin * 16u, src + (size_t)lin * 16);
    cp_commit();
}

// LN one row (128 cols) by a full warp; write split bf16 into A tile.
__device__ __forceinline__ void ln_row(char* smp, uint32_t hiOff, uint32_t loOff,
    int row, int lane, const float* x,
    float g0, float g1, float g2, float g3,
    float c0, float c1, float c2, float c3)
{
    float v0 = x[lane], v1 = x[lane+32], v2 = x[lane+64], v3 = x[lane+96];
    float s = v0 + v1 + v2 + v3;
    #pragma unroll
    for (int o = 16; o > 0; o >>= 1) s += __shfl_xor_sync(0xffffffffu, s, o);
    float mean = s * (1.0f / 128.0f);
    float d0 = v0-mean, d1 = v1-mean, d2 = v2-mean, d3 = v3-mean;
    float q = d0*d0 + d1*d1 + d2*d2 + d3*d3;
    #pragma unroll
    for (int o = 16; o > 0; o >>= 1) q += __shfl_xor_sync(0xffffffffu, q, o);
    float inv = rsqrtf(q * (1.0f / 128.0f) + 1e-5f);
    float y0 = d0*inv*g0 + c0, y1 = d1*inv*g1 + c1;
    float y2 = d2*inv*g2 + c2, y3 = d3*inv*g3 + c3;
    uint16_t* aH = (uint16_t*)(smp + hiOff);
    uint16_t* aL = (uint16_t*)(smp + loOff);
    uint16_t h;
    h = bf16bits(y0); aH[row*136 + lane]      = h; aL[row*136 + lane]      = bf16bits(y0 - bf2f(h));
    h = bf16bits(y1); aH[row*136 + lane + 32] = h; aL[row*136 + lane + 32] = bf16bits(y1 - bf2f(h));
    h = bf16bits(y2); aH[row*136 + lane + 64] = h; aL[row*136 + lane + 64] = bf16bits(y2 - bf2f(h));
    h = bf16bits(y3); aH[row*136 + lane + 96] = h; aL[row*136 + lane + 96] = bf16bits(y3 - bf2f(h));
}

// ============================================================
// Kernel W: pre-split the 6 weight matrices into tile images (runs once, tiny)
// mats: 0=wga 1=wpa 2=wgb 3=wpb 4=wog 5=wop
// ============================================================
__global__ void __launch_bounds__(512, 1) prep_w_kernel(
    const float* __restrict__ wga, const float* __restrict__ wpa,
    const float* __restrict__ wgb, const float* __restrict__ wpb,
    const float* __restrict__ wog, const float* __restrict__ wop)
{
    const float* Ws[6] = {wga, wpa, wgb, wpb, wog, wop};
    const float* W = Ws[blockIdx.x];
    unsigned char* dst = g_wt + (size_t)blockIdx.x * 69632;
    #pragma unroll
    for (int it = 0; it < 8; it++) {
        int lin = threadIdx.x + it * 512;
        int r = lin >> 5, c4 = (lin & 31) << 2;
        float4 v = *(const float4*)(W + r * 128 + c4);
        uint2 hh, ll;
        split4(v, hh, ll);
        *(uint2*)(dst + r * TSTRIDE + c4 * 2) = hh;
        *(uint2*)(dst + 34816 + r * TSTRIDE + c4 * 2) = ll;
    }
}

// ============================================================
// Kernel P: LN(z) + 5 projections.  Block = 64 rows, 512 threads, 2 CTAs/SM.
// smem: A_hi 0, A_lo 17408, W_hi 34816, W_lo 69632  = 104448
// Pair-epilogue stage overlays W: stH @34816, stL @53248 (128 x 72 elems).
// ============================================================
#define PR_AHI 0u
#define PR_ALO 17408u
#define PR_WHI 34816u
#define PR_STH 34816u
#define PR_STL 53248u
#define PR_SMEM 104448

__global__ void __launch_bounds__(512, 2) proj_kernel(
    const float* __restrict__ z, const float* __restrict__ gin, const float* __restrict__ bin,
    const float* __restrict__ bga, const float* __restrict__ bpa,
    const float* __restrict__ bgb, const float* __restrict__ bpb,
    const float* __restrict__ bog)
{
    extern __shared__ char smp[];
    const uint32_t sb = smem_u32(smp);
    const int tid = threadIdx.x, wid = tid >> 5, lane = tid & 31;

    const size_t m0 = (size_t)blockIdx.x * 64;
    const int b  = (int)(m0 >> 16);
    const int ii = (int)((m0 >> 8) & 255);
    const int k0 = (int)(m0 & 255);

    // pre-issue first weight load (wga), hidden behind LN
    load_w_async(sb + PR_WHI, 0);

    // ---- LN rows -> split A tiles (4 rows per warp) ----
    {
        const float g0 = gin[lane], g1 = gin[lane+32], g2 = gin[lane+64], g3 = gin[lane+96];
        const float c0 = bin[lane], c1 = bin[lane+32], c2 = bin[lane+64], c3 = bin[lane+96];
        #pragma unroll
        for (int r = 0; r < 4; r++) {
            int row = wid * 4 + r;
            ln_row(smp, PR_AHI, PR_ALO, row, lane, z + (m0 + row) * 128,
                   g0, g1, g2, g3, c0, c1, c2, c3);
        }
    }
    cp_wait_all();
    __syncthreads();

    const int m0w = (wid >> 2) * 16, n0w = (wid & 3) * 32;
    const uint32_t aHiW = sb + PR_AHI + (uint32_t)m0w * TSTRIDE;
    const uint32_t aLoW = sb + PR_ALO + (uint32_t)m0w * TSTRIDE;
    const uint32_t wHiN = sb + PR_WHI + (uint32_t)n0w * TSTRIDE;
    const uint32_t wLoN = wHiN + 34816u;

    // ---- two gated-pair phases (W holds the G matrix on loop entry) ----
    for (int ph = 0; ph < 2; ph++) {
        const float* bg = ph ? bgb : bga;
        const float* bp = ph ? bpb : bpa;

        float accG[4][4] = {};
        gemm16x32<8>(accG, aHiW, aLoW, wHiN, wLoN, lane);
        __syncthreads();
        load_w_async(sb + PR_WHI, ph ? 3 : 1);          // P weights
        cp_wait_all();
        __syncthreads();

        float accP[4][4] = {};
        gemm16x32<8>(accP, aHiW, aLoW, wHiN, wLoN, lane);
        __syncthreads();

        // stage transposed: stH/stL [d 128][m 72] bf16 over W region
        uint16_t* stH = (uint16_t*)(smp + PR_STH);
        uint16_t* stL = (uint16_t*)(smp + PR_STL);
        #pragma unroll
        for (int q = 0; q < 4; q++) {
            int n = n0w + q * 8 + 2 * (lane & 3);
            float2 bg2 = *(const float2*)(bg + n);
            float2 bp2 = *(const float2*)(bp + n);
            #pragma unroll
            for (int rh = 0; rh < 2; rh++) {
                int m = m0w + (lane >> 2) + rh * 8;
                float v0 = sigmoidf_(accG[q][rh*2]   + bg2.x) * (accP[q][rh*2]   + bp2.x);
                float v1 = sigmoidf_(accG[q][rh*2+1] + bg2.y) * (accP[q][rh*2+1] + bp2.y);
                uint16_t h0 = bf16bits(v0), h1 = bf16bits(v1);
                stH[n * 72 + m]       = h0;  stL[n * 72 + m]       = bf16bits(v0 - bf2f(h0));
                stH[(n + 1) * 72 + m] = h1;  stL[(n + 1) * 72 + m] = bf16bits(v1 - bf2f(h1));
            }
        }
        __syncthreads();

        __nv_bfloat16* dH = ph ? g_bt_hi : g_at_hi;
        __nv_bfloat16* dL = ph ? g_bt_lo : g_at_lo;
        #pragma unroll
        for (int it = 0; it < 4; it++) {
            int lin = tid + it * 512;          // 0..2047
            int hl  = lin >> 10;
            int idx = lin & 1023;
            int d = idx >> 3, m8 = (idx & 7) << 3;
            uint4 v = *(const uint4*)(smp + (hl ? PR_STL : PR_STH) + d * 144 + m8 * 2);
            __nv_bfloat16* dst = hl ? dL : dH;
            *(uint4*)(dst + ((size_t)(b * 128 + d)) * 65536 + (size_t)ii * 256 + k0 + m8) = v;
        }
        __syncthreads();                       // stage fully consumed
        load_w_async(sb + PR_WHI, ph ? 4 : 2); // next G (or wog)
        cp_wait_all();
        __syncthreads();
    }

    // ---- gate phase (W holds wog) ----
    float acc[4][4] = {};
    gemm16x32<8>(acc, aHiW, aLoW, wHiN, wLoN, lane);
    #pragma unroll
    for (int q = 0; q < 4; q++) {
        int n = n0w + q * 8 + 2 * (lane & 3);
        float2 bo2 = *(const float2*)(bog + n);
        #pragma unroll
        for (int rh = 0; rh < 2; rh++) {
            int m = m0w + (lane >> 2) + rh * 8;
            float2 o;
            o.x = sigmoidf_(acc[q][rh*2]   + bo2.x);
            o.y = sigmoidf_(acc[q][rh*2+1] + bo2.y);
            *(float2*)(g_gate + (m0 + m) * 128 + n) = o;
        }
    }
}

// ============================================================
// Kernel T: triangle einsum. C tile 64x128 per block, 512 threads, 2 CTAs/SM.
// K = 256 in 2 chunks of 128.  smem: A_hi 0, A_lo 17408, B_hi 34816, B_lo 69632.
// grid.x = 4096: bd = bx>>3, i0 = ((bx>>1)&3)*64, j0 = (bx&1)*128
// ============================================================
#define TR_AHI 0u
#define TR_ALO 17408u
#define TR_BHI 34816u
#define TR_BLO 69632u
#define TR_SMEM 104448

__global__ void __launch_bounds__(512, 2) tri_kernel()
{
    extern __shared__ char smp[];
    const uint32_t sb = smem_u32(smp);
    const int tid = threadIdx.x, wid = tid >> 5, lane = tid & 31;
    const int bx = blockIdx.x;
    const int bd = bx >> 3;
    const int i0 = ((bx >> 1) & 3) * 64;
    const int j0 = (bx & 1) * 128;
    const size_t base = (size_t)bd * 65536;

    const int m0w = (wid >> 2) * 16, n0w = (wid & 3) * 32;
    float acc[4][4] = {};

    for (int kb = 0; kb < 2; kb++) {
        if (kb) __syncthreads();
        #pragma unroll
        for (int it = 0; it < 12; it++) {
            int lin = tid + it * 512;          // 0..6143 (16B chunks)
            if (lin < 2048) {                  // A: 64 rows x 128 k, hi then lo
                int idx = lin & 1023;
                int row = idx >> 4, c = idx & 15;
                const __nv_bfloat16* s = (lin < 1024) ? g_at_hi : g_at_lo;
                uint32_t dst = (lin < 1024) ? TR_AHI : TR_ALO;
                cp16(sb + dst + row * TSTRIDE + c * 16,
                     s + base + (size_t)(i0 + row) * 256 + kb * 128 + c * 8);
            } else {                           // B: 128 rows x 128 k, hi then lo
                int l2 = lin - 2048;
                int idx = l2 & 2047;
                int row = idx >> 4, c = idx & 15;
                const __nv_bfloat16* s = (l2 < 2048) ? g_bt_hi : g_bt_lo;
                uint32_t dst = (l2 < 2048) ? TR_BHI : TR_BLO;
                cp16(sb + dst + row * TSTRIDE + c * 16,
                     s + base + (size_t)(j0 + row) * 256 + kb * 128 + c * 8);
            }
        }
        cp_commit();
        cp_wait_all();
        __syncthreads();
        gemm16x32<8>(acc, sb + TR_AHI + (uint32_t)m0w * TSTRIDE,
                          sb + TR_ALO + (uint32_t)m0w * TSTRIDE,
                          sb + TR_BHI + (uint32_t)n0w * TSTRIDE,
                          sb + TR_BLO + (uint32_t)n0w * TSTRIDE, lane);
    }

    #pragma unroll
    for (int q = 0; q < 4; q++) {
        int n = n0w + q * 8 + 2 * (lane & 3);
        #pragma unroll
        for (int rh = 0; rh < 2; rh++) {
            int m = m0w + (lane >> 2) + rh * 8;
            float2 o = make_float2(acc[q][rh*2], acc[q][rh*2+1]);
            *(float2*)(g_ot + base + (size_t)(i0 + m) * 256 + j0 + n) = o;
        }
    }
}

// ============================================================
// Kernel F: transpose-gather + LN + wop + gate.  64 p-rows, 512 threads, 2 CTAs/SM.
// smem: A_hi 0, A_lo 17408; X f32 [64][133] @34816 (dead after LN);
//       W_hi 34816, W_lo 69632 (overlays X).  Total 104448.
// grid.x = 4096: b = bx>>10, p0 = (bx&1023)*64
// ============================================================
#define FN_AHI 0u
#define FN_ALO 17408u
#define FN_X   34816u
#define FN_WHI 34816u
#define FN_SMEM 104448

__global__ void __launch_bounds__(512, 2) final_kernel(
    const float* __restrict__ gout, const float* __restrict__ bout,
    const float* __restrict__ bop, float* __restrict__ outp)
{
    extern __shared__ char smp[];
    const uint32_t sb = smem_u32(smp);
    const int tid = threadIdx.x, wid = tid >> 5, lane = tid & 31;
    const int b  = blockIdx.x >> 10;
    const int p0 = (blockIdx.x & 1023) * 64;

    // gather-transpose: X[p][d] <- g_ot[b][d][p0+p]
    float* X = (float*)(smp + FN_X);
    #pragma unroll
    for (int it = 0; it < 4; it++) {
        int lin = tid + it * 512;
        int d = lin >> 4, p4 = (lin & 15) << 2;
        float4 v = *(const float4*)(g_ot + ((size_t)(b * 128 + d)) * 65536 + p0 + p4);
        X[(p4 + 0) * 133 + d] = v.x;
        X[(p4 + 1) * 133 + d] = v.y;
        X[(p4 + 2) * 133 + d] = v.z;
        X[(p4 + 3) * 133 + d] = v.w;
    }
    __syncthreads();

    // LN rows of X -> split A tiles (4 rows per warp)
    {
        const float g0 = gout[lane], g1 = gout[lane+32], g2 = gout[lane+64], g3 = gout[lane+96];
        const float c0 = bout[lane], c1 = bout[lane+32], c2 = bout[lane+64], c3 = bout[lane+96];
        #pragma unroll
        for (int r = 0; r < 4; r++) {
            int row = wid * 4 + r;
            ln_row(smp, FN_AHI, FN_ALO, row, lane, X + row * 133,
                   g0, g1, g2, g3, c0, c1, c2, c3);
        }
    }
    __syncthreads();            // X fully consumed before W overlays it
    load_w_async(sb + FN_WHI, 5);
    cp_wait_all();
    __syncthreads();

    const int m0w = (wid >> 2) * 16, n0w = (wid & 3) * 32;
    float acc[4][4] = {};
    gemm16x32<8>(acc, sb + FN_AHI + (uint32_t)m0w * TSTRIDE,
                      sb + FN_ALO + (uint32_t)m0w * TSTRIDE,
                      sb + FN_WHI + (uint32_t)n0w * TSTRIDE,
                      sb + FN_WHI + 34816u + (uint32_t)n0w * TSTRIDE, lane);

    #pragma unroll
    for (int q = 0; q < 4; q++) {
        int n = n0w + q * 8 + 2 * (lane & 3);
        float2 bo2 = *(const float2*)(bop + n);
        #pragma unroll
        for (int rh = 0; rh < 2; rh++) {
            int m = m0w + (lane >> 2) + rh * 8;
            size_t gi = ((size_t)b * 65536 + p0 + m) * 128 + n;
            float2 g = *(const float2*)(g_gate + gi);
            float2 o;
            o.x = g.x * (acc[q][rh*2]   + bo2.x);
            o.y = g.y * (acc[q][rh*2+1] + bo2.y);
            *(float2*)(outp + gi) = o;
        }
    }
}

// ============================================================
// launch
// ============================================================
extern "C" void kernel_launch(void* const* d_in, const int* in_sizes, int n_in,
                              void* d_out, int out_size)
{
    const float* z    = (const float*)d_in[0];
    const float* gin  = (const float*)d_in[1];
    const float* bin  = (const float*)d_in[2];
    const float* wpa  = (const float*)d_in[3];
    const float* bpa  = (const float*)d_in[4];
    const float* wga  = (const float*)d_in[5];
    const float* bga  = (const float*)d_in[6];
    const float* wpb  = (const float*)d_in[7];
    const float* bpb  = (const float*)d_in[8];
    const float* wgb  = (const float*)d_in[9];
    const float* bgb  = (const float*)d_in[10];
    const float* gout = (const float*)d_in[11];
    const float* bout = (const float*)d_in[12];
    const float* wop  = (const float*)d_in[13];
    const float* bop  = (const float*)d_in[14];
    const float* wog  = (const float*)d_in[15];
    const float* bog  = (const float*)d_in[16];
    float* outp = (float*)d_out;

    cudaFuncSetAttribute(proj_kernel,  cudaFuncAttributeMaxDynamicSharedMemorySize, PR_SMEM);
    cudaFuncSetAttribute(tri_kernel,   cudaFuncAttributeMaxDynamicSharedMemorySize, TR_SMEM);
    cudaFuncSetAttribute(final_kernel, cudaFuncAttributeMaxDynamicSharedMemorySize, FN_SMEM);

    prep_w_kernel<<<6, 512>>>(wga, wpa, wgb, wpb, wog, wop);
    proj_kernel<<<4096, 512, PR_SMEM>>>(z, gin, bin, bga, bpa, bgb, bpb, bog);
    tri_kernel<<<4096, 512, TR_SMEM>>>();
    final_kernel<<<4096, 512, FN_SMEM>>>(gout, bout, bop, outp);
}

// round 7
// speedup vs baseline: 2.9236x; 1.0072x over previous
#include <cuda_runtime.h>
#include <cuda_bf16.h>
#include <stdint.h>

#define ELEMS ((size_t)4*256*256*128)   // 33.5M

// ---------------- scratch ----------------
__device__ __align__(16) __nv_bfloat16 g_at_hi[ELEMS];
__device__ __align__(16) __nv_bfloat16 g_at_lo[ELEMS];
__device__ __align__(16) __nv_bfloat16 g_bt_hi[ELEMS];
__device__ __align__(16) __nv_bfloat16 g_bt_lo[ELEMS];
__device__ __align__(16) float g_gate[ELEMS];
__device__ __align__(16) float g_ot[ELEMS];
// pre-split weight tile images: 6 mats x (hi 34816 B + lo 34816 B), 272 B row stride
__device__ __align__(16) unsigned char g_wt[6 * 69632];

// ---------------- helpers ----------------
__device__ __forceinline__ uint32_t smem_u32(const void* p){
    uint32_t a;
    asm("{ .reg .u64 t; cvta.to.shared.u64 t, %1; cvt.u32.u64 %0, t; }" : "=r"(a) : "l"(p));
    return a;
}
__device__ __forceinline__ void ldsm_x4(uint32_t* r, uint32_t a){
    asm volatile("ldmatrix.sync.aligned.m8n8.x4.shared.b16 {%0,%1,%2,%3}, [%4];"
        : "=r"(r[0]), "=r"(r[1]), "=r"(r[2]), "=r"(r[3]) : "r"(a));
}
__device__ __forceinline__ void mma16816(float* c, const uint32_t* a, const uint32_t* b){
    asm volatile("mma.sync.aligned.m16n8k16.row.col.f32.bf16.bf16.f32 "
        "{%0,%1,%2,%3}, {%4,%5,%6,%7}, {%8,%9}, {%0,%1,%2,%3};"
        : "+f"(c[0]), "+f"(c[1]), "+f"(c[2]), "+f"(c[3])
        : "r"(a[0]), "r"(a[1]), "r"(a[2]), "r"(a[3]), "r"(b[0]), "r"(b[1]));
}
__device__ __forceinline__ void cp16(uint32_t dst, const void* src){
    asm volatile("cp.async.cg.shared.global [%0], [%1], 16;" :: "r"(dst), "l"(src));
}
__device__ __forceinline__ void cp_commit(){
    asm volatile("cp.async.commit_group;" ::: "memory");
}
__device__ __forceinline__ void cp_wait0(){
    asm volatile("cp.async.wait_group 0;" ::: "memory");
}
__device__ __forceinline__ float sigmoidf_(float x){ return 1.0f / (1.0f + __expf(-x)); }
__device__ __forceinline__ uint16_t bf16bits(float v){
    __nv_bfloat16 h = __float2bfloat16(v);
    return *reinterpret_cast<uint16_t*>(&h);
}
__device__ __forceinline__ float bf2f(uint16_t u){
    __nv_bfloat16 h = *reinterpret_cast<__nv_bfloat16*>(&u);
    return __bfloat162float(h);
}
__device__ __forceinline__ void split4(float4 v, uint2& hh, uint2& ll){
    uint16_t h0=bf16bits(v.x), h1=bf16bits(v.y), h2=bf16bits(v.z), h3=bf16bits(v.w);
    uint16_t l0=bf16bits(v.x-bf2f(h0)), l1=bf16bits(v.y-bf2f(h1)),
             l2=bf16bits(v.z-bf2f(h2)), l3=bf16bits(v.w-bf2f(h3));
    hh.x = (uint32_t)h0 | ((uint32_t)h1<<16); hh.y = (uint32_t)h2 | ((uint32_t)h3<<16);
    ll.x = (uint32_t)l0 | ((uint32_t)l1<<16); ll.y = (uint32_t)l2 | ((uint32_t)l3<<16);
}

#define TSTRIDE 272u   // full-K (128) bf16 tile row stride in bytes
#define HSTRIDE 144u   // half-K (64)  bf16 tile row stride in bytes

// 32x32 warp-tile split GEMM over 64 K (4 ksteps). acc[2 m-subtiles][4 n-octets][4].
// 3 terms sequenced (AhBh, AlBh, AhBl) with B-fragment register reuse.
template<int SA, int SB>
__device__ __forceinline__ void gemm32(float (&acc)[2][4][4],
    uint32_t aHi, uint32_t aLo, uint32_t bHi, uint32_t bLo, int lane)
{
    const uint32_t aOff = (uint32_t)(lane & 15) * SA + (uint32_t)((lane >> 4) << 4);
    const uint32_t bOff = (uint32_t)(((lane >> 4) << 3) + (lane & 7)) * SB
                        + (uint32_t)(((lane >> 3) & 1) << 4);
    #pragma unroll
    for (int ks = 0; ks < 4; ks++) {
        const uint32_t ka = aOff + (uint32_t)ks * 32u;
        const uint32_t kb = bOff + (uint32_t)ks * 32u;
        uint32_t ah[2][4], al[2][4], bb[2][4];
        ldsm_x4(ah[0], aHi + ka);
        ldsm_x4(ah[1], aHi + 16u * SA + ka);
        ldsm_x4(bb[0], bHi + kb);
        ldsm_x4(bb[1], bHi + 16u * SB + kb);
        #pragma unroll
        for (int mt = 0; mt < 2; mt++)
            #pragma unroll
            for (int q = 0; q < 4; q++)
                mma16816(acc[mt][q], ah[mt], &bb[q >> 1][(q & 1) << 1]);
        ldsm_x4(al[0], aLo + ka);
        ldsm_x4(al[1], aLo + 16u * SA + ka);
        #pragma unroll
        for (int mt = 0; mt < 2; mt++)
            #pragma unroll
            for (int q = 0; q < 4; q++)
                mma16816(acc[mt][q], al[mt], &bb[q >> 1][(q & 1) << 1]);
        ldsm_x4(bb[0], bLo + kb);
        ldsm_x4(bb[1], bLo + 16u * SB + kb);
        #pragma unroll
        for (int mt = 0; mt < 2; mt++)
            #pragma unroll
            for (int q = 0; q < 4; q++)
                mma16816(acc[mt][q], ah[mt], &bb[q >> 1][(q & 1) << 1]);
    }
}

// async copy one half-K (64k) weight tile (hi 18432 + lo 18432 B) into smem
__device__ __forceinline__ void load_w_half(uint32_t dst, int mat, int half){
    const unsigned char* src = g_wt + (size_t)mat * 69632 + half * 128;
    #pragma unroll
    for (int it = 0; it < 8; it++) {
        int lin = threadIdx.x + it * 256;      // 0..2047
        int plane = lin >> 10, idx = lin & 1023;
        int r = idx >> 3, c = idx & 7;
        cp16(dst + (uint32_t)plane * 18432u + (uint32_t)r * HSTRIDE + (uint32_t)c * 16u,
             src + (size_t)plane * 34816 + (size_t)r * 272 + c * 16);
    }
    cp_commit();
}

// LN one row (128 cols) by a full warp; write split bf16 into A tile (272-stride).
__device__ __forceinline__ void ln_row(char* smp, uint32_t hiOff, uint32_t loOff,
    int row, int lane, const float* x,
    float g0, float g1, float g2, float g3,
    float c0, float c1, float c2, float c3)
{
    float v0 = x[lane], v1 = x[lane+32], v2 = x[lane+64], v3 = x[lane+96];
    float s = v0 + v1 + v2 + v3;
    #pragma unroll
    for (int o = 16; o > 0; o >>= 1) s += __shfl_xor_sync(0xffffffffu, s, o);
    float mean = s * (1.0f / 128.0f);
    float d0 = v0-mean, d1 = v1-mean, d2 = v2-mean, d3 = v3-mean;
    float q = d0*d0 + d1*d1 + d2*d2 + d3*d3;
    #pragma unroll
    for (int o = 16; o > 0; o >>= 1) q += __shfl_xor_sync(0xffffffffu, q, o);
    float inv = rsqrtf(q * (1.0f / 128.0f) + 1e-5f);
    float y0 = d0*inv*g0 + c0, y1 = d1*inv*g1 + c1;
    float y2 = d2*inv*g2 + c2, y3 = d3*inv*g3 + c3;
    uint16_t* aH = (uint16_t*)(smp + hiOff);
    uint16_t* aL = (uint16_t*)(smp + loOff);
    uint16_t h;
    h = bf16bits(y0); aH[row*136 + lane]      = h; aL[row*136 + lane]      = bf16bits(y0 - bf2f(h));
    h = bf16bits(y1); aH[row*136 + lane + 32] = h; aL[row*136 + lane + 32] = bf16bits(y1 - bf2f(h));
    h = bf16bits(y2); aH[row*136 + lane + 64] = h; aL[row*136 + lane + 64] = bf16bits(y2 - bf2f(h));
    h = bf16bits(y3); aH[row*136 + lane + 96] = h; aL[row*136 + lane + 96] = bf16bits(y3 - bf2f(h));
}

// ============================================================
// Kernel W: pre-split the 6 weight matrices (once; 0=wga 1=wpa 2=wgb 3=wpb 4=wog 5=wop)
// ============================================================
__global__ void __launch_bounds__(512, 1) prep_w_kernel(
    const float* __restrict__ wga, const float* __restrict__ wpa,
    const float* __restrict__ wgb, const float* __restrict__ wpb,
    const float* __restrict__ wog, const float* __restrict__ wop)
{
    const float* Ws[6] = {wga, wpa, wgb, wpb, wog, wop};
    const float* W = Ws[blockIdx.x];
    unsigned char* dst = g_wt + (size_t)blockIdx.x * 69632;
    #pragma unroll
    for (int it = 0; it < 8; it++) {
        int lin = threadIdx.x + it * 512;
        int r = lin >> 5, c4 = (lin & 31) << 2;
        float4 v = *(const float4*)(W + r * 128 + c4);
        uint2 hh, ll;
        split4(v, hh, ll);
        *(uint2*)(dst + r * TSTRIDE + c4 * 2) = hh;
        *(uint2*)(dst + 34816 + r * TSTRIDE + c4 * 2) = ll;
    }
}

// ============================================================
// Kernel P: LN(z) + 5 projections.  64 rows, 256 threads (8 warps, 2m x 4n), 2 CTAs/SM.
// smem: A_hi 0, A_lo 17408, WBUF0 34816 (36864), WBUF1 71680 (36864) = 108544.
// Pair epilogue stages into WBUF1; next-phase W prefetch into WBUF0 overlaps the store.
// ============================================================
#define PR_AHI 0u
#define PR_ALO 17408u
#define PR_WB0 34816u
#define PR_WB1 71680u
#define PR_SMEM 108544

__global__ void __launch_bounds__(256, 2) proj_kernel(
    const float* __restrict__ z, const float* __restrict__ gin, const float* __restrict__ bin,
    const float* __restrict__ bga, const float* __restrict__ bpa,
    const float* __restrict__ bgb, const float* __restrict__ bpb,
    const float* __restrict__ bog)
{
    extern __shared__ char smp[];
    const uint32_t sb = smem_u32(smp);
    const int tid = threadIdx.x, wid = tid >> 5, lane = tid & 31;

    const size_t m0 = (size_t)blockIdx.x * 64;
    const int b  = (int)(m0 >> 16);
    const int ii = (int)((m0 >> 8) & 255);
    const int k0 = (int)(m0 & 255);

    load_w_half(sb + PR_WB0, 0, 0);                 // wga h0, hidden behind LN

    {   // LN rows -> split A tiles (8 rows per warp)
        const float g0 = gin[lane], g1 = gin[lane+32], g2 = gin[lane+64], g3 = gin[lane+96];
        const float c0 = bin[lane], c1 = bin[lane+32], c2 = bin[lane+64], c3 = bin[lane+96];
        #pragma unroll
        for (int r = 0; r < 8; r++) {
            int row = wid * 8 + r;
            ln_row(smp, PR_AHI, PR_ALO, row, lane, z + (m0 + row) * 128,
                   g0, g1, g2, g3, c0, c1, c2, c3);
        }
    }
    cp_wait0(); __syncthreads();

    const int m0w = (wid >> 2) * 32, n0w = (wid & 3) * 32;
    const uint32_t aH0 = sb + PR_AHI + (uint32_t)m0w * TSTRIDE;
    const uint32_t aL0 = sb + PR_ALO + (uint32_t)m0w * TSTRIDE;
    const uint32_t b0n = sb + PR_WB0 + (uint32_t)n0w * HSTRIDE;
    const uint32_t b1n = sb + PR_WB1 + (uint32_t)n0w * HSTRIDE;

    // ---- two gated-pair phases (invariant at entry: WB0 = (gmat, h0), no cp pending) ----
    for (int ph = 0; ph < 2; ph++) {
        const int gmat = ph ? 2 : 0, pmat = ph ? 3 : 1;
        const float* bg = ph ? bgb : bga;
        const float* bp = ph ? bpb : bpa;

        float accG[2][4][4] = {}, accP[2][4][4] = {};

        load_w_half(sb + PR_WB1, gmat, 1);
        gemm32<TSTRIDE, HSTRIDE>(accG, aH0, aL0, b0n, b0n + 18432u, lane);
        cp_wait0(); __syncthreads();

        load_w_half(sb + PR_WB0, pmat, 0);
        gemm32<TSTRIDE, HSTRIDE>(accG, aH0 + 128u, aL0 + 128u, b1n, b1n + 18432u, lane);
        cp_wait0(); __syncthreads();

        load_w_half(sb + PR_WB1, pmat, 1);
        gemm32<TSTRIDE, HSTRIDE>(accP, aH0, aL0, b0n, b0n + 18432u, lane);
        cp_wait0(); __syncthreads();

        gemm32<TSTRIDE, HSTRIDE>(accP, aH0 + 128u, aL0 + 128u, b1n, b1n + 18432u, lane);
        __syncthreads();

        // stage transposed into WBUF1: stH/stL [d 128][m 72] bf16
        uint16_t* stH = (uint16_t*)(smp + PR_WB1);
        uint16_t* stL = (uint16_t*)(smp + PR_WB1 + 18432u);
        #pragma unroll
        for (int mt = 0; mt < 2; mt++)
            #pragma unroll
            for (int q = 0; q < 4; q++) {
                int n = n0w + q * 8 + 2 * (lane & 3);
                float2 bg2 = *(const float2*)(bg + n);
                float2 bp2 = *(const float2*)(bp + n);
                #pragma unroll
                for (int rh = 0; rh < 2; rh++) {
                    int m = m0w + mt * 16 + (lane >> 2) + rh * 8;
                    float v0 = sigmoidf_(accG[mt][q][rh*2]   + bg2.x) * (accP[mt][q][rh*2]   + bp2.x);
                    float v1 = sigmoidf_(accG[mt][q][rh*2+1] + bg2.y) * (accP[mt][q][rh*2+1] + bp2.y);
                    uint16_t h0 = bf16bits(v0), h1 = bf16bits(v1);
                    stH[n * 72 + m]       = h0;  stL[n * 72 + m]       = bf16bits(v0 - bf2f(h0));
                    stH[(n + 1) * 72 + m] = h1;  stL[(n + 1) * 72 + m] = bf16bits(v1 - bf2f(h1));
                }
            }
        __syncthreads();

        load_w_half(sb + PR_WB0, ph ? 4 : 2, 0);    // next phase h0 — overlaps the store below

        __nv_bfloat16* dH = ph ? g_bt_hi : g_at_hi;
        __nv_bfloat16* dL = ph ? g_bt_lo : g_at_lo;
        #pragma unroll
        for (int it = 0; it < 8; it++) {
            int lin = tid + it * 256;               // 0..2047
            int hl  = lin >> 10;
            int idx = lin & 1023;
            int d = idx >> 3, m8 = (idx & 7) << 3;
            uint4 v = *(const uint4*)(smp + PR_WB1 + (uint32_t)hl * 18432u + d * HSTRIDE + m8 * 2);
            __nv_bfloat16* dst = hl ? dL : dH;
            *(uint4*)(dst + ((size_t)(b * 128 + d)) * 65536 + (size_t)ii * 256 + k0 + m8) = v;
        }
        cp_wait0(); __syncthreads();
    }

    // ---- gate phase (WB0 = wog h0) ----
    float acc[2][4][4] = {};
    load_w_half(sb + PR_WB1, 4, 1);
    gemm32<TSTRIDE, HSTRIDE>(acc, aH0, aL0, b0n, b0n + 18432u, lane);
    cp_wait0(); __syncthreads();
    gemm32<TSTRIDE, HSTRIDE>(acc, aH0 + 128u, aL0 + 128u, b1n, b1n + 18432u, lane);

    #pragma unroll
    for (int mt = 0; mt < 2; mt++)
        #pragma unroll
        for (int q = 0; q < 4; q++) {
            int n = n0w + q * 8 + 2 * (lane & 3);
            float2 bo2 = *(const float2*)(bog + n);
            #pragma unroll
            for (int rh = 0; rh < 2; rh++) {
                int m = m0w + mt * 16 + (lane >> 2) + rh * 8;
                float2 o;
                o.x = sigmoidf_(acc[mt][q][rh*2]   + bo2.x);
                o.y = sigmoidf_(acc[mt][q][rh*2+1] + bo2.y);
                *(float2*)(g_gate + (m0 + m) * 128 + n) = o;
            }
        }
}

// ============================================================
// Kernel T: triangle einsum. C tile 64x128, 256 threads (8 warps), 2 CTAs/SM.
// K = 256 in 4 chunks of 64, double-buffered (2 x 55296 = 110592 B).
// Buffer layout: A_hi 0, A_lo 9216, B_hi 18432, B_lo 36864.
// grid.x = 4096: bd = bx>>3, i0 = ((bx>>1)&3)*64, j0 = (bx&1)*128
// ============================================================
#define TR_BUFSZ 55296u
#define TR_SMEM  110592

__device__ __forceinline__ void tri_load_chunk(uint32_t bufBase, size_t base,
                                               int i0, int j0, int kc)
{
    #pragma unroll
    for (int it = 0; it < 12; it++) {
        int lin = threadIdx.x + it * 256;          // 0..3071
        if (lin < 1024) {                          // A: 64 rows, hi/lo
            int plane = lin >> 9, idx = lin & 511;
            int r = idx >> 3, c = idx & 7;
            const __nv_bfloat16* s = plane ? g_at_lo : g_at_hi;
            cp16(bufBase + (uint32_t)plane * 9216u + (uint32_t)r * HSTRIDE + (uint32_t)c * 16u,
                 s + base + (size_t)(i0 + r) * 256 + kc * 64 + c * 8);
        } else {                                   // B: 128 rows, hi/lo
            int l2 = lin - 1024;
            int plane = l2 >> 10, idx = l2 & 1023;
            int r = idx >> 3, c = idx & 7;
            const __nv_bfloat16* s = plane ? g_bt_lo : g_bt_hi;
            cp16(bufBase + 18432u + (uint32_t)plane * 18432u + (uint32_t)r * HSTRIDE + (uint32_t)c * 16u,
                 s + base + (size_t)(j0 + r) * 256 + kc * 64 + c * 8);
        }
    }
    cp_commit();
}

__global__ void __launch_bounds__(256, 2) tri_kernel()
{
    extern __shared__ char smp[];
    const uint32_t sb = smem_u32(smp);
    const int tid = threadIdx.x, wid = tid >> 5, lane = tid & 31;
    const int bx = blockIdx.x;
    const int bd = bx >> 3;
    const int i0 = ((bx >> 1) & 3) * 64;
    const int j0 = (bx & 1) * 128;
    const size_t base = (size_t)bd * 65536;

    const int m0w = (wid >> 2) * 32, n0w = (wid & 3) * 32;
    float acc[2][4][4] = {};

    tri_load_chunk(sb, base, i0, j0, 0);
    #pragma unroll
    for (int kc = 0; kc < 4; kc++) {
        cp_wait0(); __syncthreads();
        if (kc < 3) tri_load_chunk(sb + ((kc + 1) & 1) * TR_BUFSZ, base, i0, j0, kc + 1);
        const uint32_t bf = sb + (kc & 1) * TR_BUFSZ;
        gemm32<HSTRIDE, HSTRIDE>(acc,
            bf + (uint32_t)m0w * HSTRIDE, bf + 9216u + (uint32_t)m0w * HSTRIDE,
            bf + 18432u + (uint32_t)n0w * HSTRIDE, bf + 36864u + (uint32_t)n0w * HSTRIDE, lane);
    }

    #pragma unroll
    for (int mt = 0; mt < 2; mt++)
        #pragma unroll
        for (int q = 0; q < 4; q++) {
            int n = n0w + q * 8 + 2 * (lane & 3);
            #pragma unroll
            for (int rh = 0; rh < 2; rh++) {
                int m = m0w + mt * 16 + (lane >> 2) + rh * 8;
                float2 o = make_float2(acc[mt][q][rh*2], acc[mt][q][rh*2+1]);
                *(float2*)(g_ot + base + (size_t)(i0 + m) * 256 + j0 + n) = o;
            }
        }
}

// ============================================================
// Kernel F: transpose-gather + LN + wop + gate.  64 p-rows, 256 threads, 3 CTAs/SM.
// smem: A_hi 0, A_lo 17408; X f32 [64][133] @34816 (dead after LN);
//       W halves overlay X: whi 34816, wlo 53248.  Total 71680.
// grid.x = 4096: b = bx>>10, p0 = (bx&1023)*64
// ============================================================
#define FN_AHI 0u
#define FN_ALO 17408u
#define FN_X   34816u
#define FN_W   34816u
#define FN_SMEM 71680

__global__ void __launch_bounds__(256, 3) final_kernel(
    const float* __restrict__ gout, const float* __restrict__ bout,
    const float* __restrict__ bop, float* __restrict__ outp)
{
    extern __shared__ char smp[];
    const uint32_t sb = smem_u32(smp);
    const int tid = threadIdx.x, wid = tid >> 5, lane = tid & 31;
    const int b  = blockIdx.x >> 10;
    const int p0 = (blockIdx.x & 1023) * 64;

    // gather-transpose: X[p][d] <- g_ot[b][d][p0+p]
    float* X = (float*)(smp + FN_X);
    #pragma unroll
    for (int it = 0; it < 8; it++) {
        int lin = tid + it * 256;
        int d = lin >> 4, p4 = (lin & 15) << 2;
        float4 v = *(const float4*)(g_ot + ((size_t)(b * 128 + d)) * 65536 + p0 + p4);
        X[(p4 + 0) * 133 + d] = v.x;
        X[(p4 + 1) * 133 + d] = v.y;
        X[(p4 + 2) * 133 + d] = v.z;
        X[(p4 + 3) * 133 + d] = v.w;
    }
    __syncthreads();

    // LN rows of X -> split A tiles (8 rows per warp)
    {
        const float g0 = gout[lane], g1 = gout[lane+32], g2 = gout[lane+64], g3 = gout[lane+96];
        const float c0 = bout[lane], c1 = bout[lane+32], c2 = bout[lane+64], c3 = bout[lane+96];
        #pragma unroll
        for (int r = 0; r < 8; r++) {
            int row = wid * 8 + r;
            ln_row(smp, FN_AHI, FN_ALO, row, lane, X + row * 133,
                   g0, g1, g2, g3, c0, c1, c2, c3);
        }
    }
    __syncthreads();            // X fully consumed before W overlays it

    const int m0w = (wid >> 2) * 32, n0w = (wid & 3) * 32;
    const uint32_t aH0 = sb + FN_AHI + (uint32_t)m0w * TSTRIDE;
    const uint32_t aL0 = sb + FN_ALO + (uint32_t)m0w * TSTRIDE;
    const uint32_t wn  = sb + FN_W + (uint32_t)n0w * HSTRIDE;

    float acc[2][4][4] = {};
    load_w_half(sb + FN_W, 5, 0);
    cp_wait0(); __syncthreads();
    gemm32<TSTRIDE, HSTRIDE>(acc, aH0, aL0, wn, wn + 18432u, lane);
    __syncthreads();
    load_w_half(sb + FN_W, 5, 1);
    cp_wait0(); __syncthreads();
    gemm32<TSTRIDE, HSTRIDE>(acc, aH0 + 128u, aL0 + 128u, wn, wn + 18432u, lane);

    #pragma unroll
    for (int mt = 0; mt < 2; mt++)
        #pragma unroll
        for (int q = 0; q < 4; q++) {
            int n = n0w + q * 8 + 2 * (lane & 3);
            float2 bo2 = *(const float2*)(bop + n);
            #pragma unroll
            for (int rh = 0; rh < 2; rh++) {
                int m = m0w + mt * 16 + (lane >> 2) + rh * 8;
                size_t gi = ((size_t)b * 65536 + p0 + m) * 128 + n;
                float2 g = *(const float2*)(g_gate + gi);
                float2 o;
                o.x = g.x * (acc[mt][q][rh*2]   + bo2.x);
                o.y = g.y * (acc[mt][q][rh*2+1] + bo2.y);
                *(float2*)(outp + gi) = o;
            }
        }
}

// ============================================================
// launch
// ============================================================
extern "C" void kernel_launch(void* const* d_in, const int* in_sizes, int n_in,
                              void* d_out, int out_size)
{
    const float* z    = (const float*)d_in[0];
    const float* gin  = (const float*)d_in[1];
    const float* bin  = (const float*)d_in[2];
    const float* wpa  = (const float*)d_in[3];
    const float* bpa  = (const float*)d_in[4];
    const float* wga  = (const float*)d_in[5];
    const float* bga  = (const float*)d_in[6];
    const float* wpb  = (const float*)d_in[7];
    const float* bpb  = (const float*)d_in[8];
    const float* wgb  = (const float*)d_in[9];
    const float* bgb  = (const float*)d_in[10];
    const float* gout = (const float*)d_in[11];
    const float* bout = (const float*)d_in[12];
    const float* wop  = (const float*)d_in[13];
    const float* bop  = (const float*)d_in[14];
    const float* wog  = (const float*)d_in[15];
    const float* bog  = (const float*)d_in[16];
    float* outp = (float*)d_out;

    cudaFuncSetAttribute(proj_kernel,  cudaFuncAttributeMaxDynamicSharedMemorySize, PR_SMEM);
    cudaFuncSetAttribute(tri_kernel,   cudaFuncAttributeMaxDynamicSharedMemorySize, TR_SMEM);
    cudaFuncSetAttribute(final_kernel, cudaFuncAttributeMaxDynamicSharedMemorySize, FN_SMEM);

    prep_w_kernel<<<6, 512>>>(wga, wpa, wgb, wpb, wog, wop);
    proj_kernel<<<4096, 256, PR_SMEM>>>(z, gin, bin, bga, bpa, bgb, bpb, bog);
    tri_kernel<<<4096, 256, TR_SMEM>>>();
    final_kernel<<<4096, 256, FN_SMEM>>>(gout, bout, bop, outp);
}